// round 6
// baseline (speedup 1.0000x reference)
#include <cuda_runtime.h>
#include <math.h>

#define NB 128
#define NN 4096
#define KK 15
#define EPSV 0.1f
#define SMALLV 1e-20f
#define MUV 2.44140625e-4f   /* 1/4096 */
#define NU0 (4081.0f/4096.0f)
#define NITER 200

typedef unsigned long long ull;

// ---------------- device scratch (static, no allocation) ----------------
__device__ float g_sig[NB * KK * NN];   // sigmoid+SMALL, layout [b][j][i]
__device__ float g_colsum[NB * KK];     // per-(b,j) column sums of sig
__device__ float g_w[NB * 16];          // initial Sinkhorn state w_m
__device__ float g_t[NB * NN];          // t_i from final iteration
__device__ float g_mx[256], g_mn[256];
__device__ int   g_fl[256];
__device__ double g_norm;

struct Par { float filled, invCmax, alpha, inv_tau, c_exp2; };
__device__ Par g_P;

// ---------------- helpers ----------------
__device__ __forceinline__ float warp_sum(float v) {
#pragma unroll
    for (int o = 16; o > 0; o >>= 1) v += __shfl_xor_sync(0xffffffffu, v, o);
    return v;
}
__device__ __forceinline__ float warp_max(float v) {
#pragma unroll
    for (int o = 16; o > 0; o >>= 1) v = fmaxf(v, __shfl_xor_sync(0xffffffffu, v, o));
    return v;
}
__device__ __forceinline__ float warp_min(float v) {
#pragma unroll
    for (int o = 16; o > 0; o >>= 1) v = fminf(v, __shfl_xor_sync(0xffffffffu, v, o));
    return v;
}
__device__ __forceinline__ int warp_or(int v) {
#pragma unroll
    for (int o = 16; o > 0; o >>= 1) v |= __shfl_xor_sync(0xffffffffu, v, o);
    return v;
}
__device__ __forceinline__ float rcpa(float x) {
    float y; asm("rcp.approx.f32 %0, %1;" : "=f"(y) : "f"(x)); return y;
}
__device__ __forceinline__ float fixs(float s) {
    return (isinf(s) && s < 0.0f) ? g_P.filled : s;
}

// ---------------- packed f32x2 (sm_103a) ----------------
__device__ __forceinline__ ull pk2(float lo, float hi) {
    ull r; asm("mov.b64 %0, {%1,%2};" : "=l"(r) : "f"(lo), "f"(hi)); return r;
}
__device__ __forceinline__ void upk2(float& lo, float& hi, ull v) {
    asm("mov.b64 {%0,%1}, %2;" : "=f"(lo), "=f"(hi) : "l"(v));
}
__device__ __forceinline__ ull fma2(ull a, ull b, ull c) {
    ull d; asm("fma.rn.f32x2 %0, %1, %2, %3;" : "=l"(d) : "l"(a), "l"(b), "l"(c)); return d;
}
__device__ __forceinline__ ull mul2(ull a, ull b) {
    ull d; asm("mul.rn.f32x2 %0, %1, %2;" : "=l"(d) : "l"(a), "l"(b)); return d;
}
__device__ __forceinline__ ull add2(ull a, ull b) {
    ull d; asm("add.rn.f32x2 %0, %1, %2;" : "=l"(d) : "l"(a), "l"(b)); return d;
}

// ---------------- A1: global min/max partials ----------------
__global__ void kA1(const float* __restrict__ scores) {
    int tid = threadIdx.x;
    int base = blockIdx.x * 2048 + tid * 8;
    const float4* p4 = reinterpret_cast<const float4*>(scores + base);
    float4 a = p4[0], b = p4[1];
    float vs[8] = {a.x, a.y, a.z, a.w, b.x, b.y, b.z, b.w};
    float mx = -3.4e38f, mn = 3.4e38f; int fl = 0;
#pragma unroll
    for (int t = 0; t < 8; t++) {
        float x = vs[t];
        if (isinf(x) && x < 0.0f) fl = 1;
        else mn = fminf(mn, x);
        mx = fmaxf(mx, x);
    }
    mx = warp_max(mx); mn = warp_min(mn); fl = warp_or(fl);
    __shared__ float smx[8], smn[8]; __shared__ int sfl[8];
    int lane = tid & 31, wid = tid >> 5;
    if (!lane) { smx[wid] = mx; smn[wid] = mn; sfl[wid] = fl; }
    __syncthreads();
    if (tid == 0) {
        for (int w = 1; w < 8; w++) { mx = fmaxf(mx, smx[w]); mn = fminf(mn, smn[w]); fl |= sfl[w]; }
        g_mx[blockIdx.x] = mx; g_mn[blockIdx.x] = mn; g_fl[blockIdx.x] = fl;
    }
}

// ---------------- A2: finalize scalar params ----------------
__global__ void kA2(const float* __restrict__ tau) {
    int tid = threadIdx.x, lane = tid & 31, wid = tid >> 5;
    float mx = g_mx[tid], mn = g_mn[tid]; int fl = g_fl[tid];
    mx = warp_max(mx); mn = warp_min(mn); fl = warp_or(fl);
    __shared__ float smx[8], smn[8]; __shared__ int sfl[8];
    if (!lane) { smx[wid] = mx; smn[wid] = mn; sfl[wid] = fl; }
    __syncthreads();
    if (tid == 0) {
        for (int w = 1; w < 8; w++) { mx = fmaxf(mx, smx[w]); mn = fminf(mn, smn[w]); fl |= sfl[w]; }
        float filled = mn - (mx - mn);
        float lo = fl ? filled : mn;
        float d1 = lo - 15.0f, d2 = mx - 15.0f;
        float Cmax = fmaxf(fmaxf(lo * lo, d1 * d1), fmaxf(mx * mx, d2 * d2));
        float invC = 1.0f / Cmax;
        Par P;
        P.filled = filled; P.invCmax = invC; P.alpha = 10.0f * invC;
        P.inv_tau = 1.0f / tau[0];
        P.c_exp2 = 2.0f * (10.0f * invC) * 1.4426950408889634f;
        g_P = P;
        g_norm = 0.0;
    }
}

// ---------------- fused prepass: top-15, sigmoids+colsums, rank-5 warm start ----------------
__global__ __launch_bounds__(512) void kPre(const float* __restrict__ scores,
                                            const float* __restrict__ w1,
                                            const float* __restrict__ w2) {
    int b = blockIdx.x, tid = threadIdx.x, lane = tid & 31, wid = tid >> 5;
    __shared__ float stv[KK];
    __shared__ float swm[16];
    __shared__ float sbc;
    __shared__ int claim;
    __shared__ float scs[16][KK];
    __shared__ float sinv[KK], lc[KK];
    __shared__ float sy[16][5];
    __shared__ float yf[5];
    __shared__ float gg[KK];

    // ---- phase A: top-15 via 15 masked argmax rounds ----
    {
        const float4* p4 = reinterpret_cast<const float4*>(scores + b * NN) + tid * 2;
        float4 a = p4[0], c4 = p4[1];
        float v[8] = {a.x, a.y, a.z, a.w, c4.x, c4.y, c4.z, c4.w};
#pragma unroll
        for (int e = 0; e < 8; e++) v[e] = fixs(v[e]);
        for (int r = 0; r < KK; r++) {
            float lm = v[0];
#pragma unroll
            for (int e = 1; e < 8; e++) lm = fmaxf(lm, v[e]);
            lm = warp_max(lm);
            if (!lane) swm[wid] = lm;
            __syncthreads();
            if (tid == 0) {
                float m = swm[0];
                for (int w = 1; w < 16; w++) m = fmaxf(m, swm[w]);
                sbc = m; claim = 0;
                stv[r] = m;
            }
            __syncthreads();
            float m = sbc;
            int idx = -1;
#pragma unroll
            for (int e = 0; e < 8; e++) if (idx < 0 && v[e] == m) idx = e;
            if (idx >= 0) {
                int old = atomicAdd(&claim, 1);
                if (old == 0) v[idx] = -3.4e38f;
            }
        }
    }
    __syncthreads();

    // ---- phase B: sigmoids + column sums ----
    {
        float itau = g_P.inv_tau;
        float cs[KK];
#pragma unroll
        for (int j = 0; j < KK; j++) cs[j] = 0.0f;
        for (int e = 0; e < 8; e++) {
            int i = tid + e * 512;
            float s = fixs(scores[b * NN + i]);
#pragma unroll
            for (int j = 0; j < KK; j++) {
                float d = fabsf(stv[j] - s) * itau;
                float ex = __expf(d);
                float sg = rcpa(1.0f + ex) + SMALLV;
                g_sig[(b * KK + j) * NN + i] = sg;
                cs[j] += sg;
            }
        }
#pragma unroll
        for (int j = 0; j < KK; j++) cs[j] = warp_sum(cs[j]);
        if (!lane) {
#pragma unroll
            for (int j = 0; j < KK; j++) scs[wid][j] = cs[j];
        }
        __syncthreads();
        if (tid < KK) {
            float a = 0.0f;
            for (int w = 0; w < 16; w++) a += scs[w][tid];
            g_colsum[b * KK + tid] = a;
            sinv[tid] = 1.0f / a;
            lc[tid] = EPSV * __logf(4096.0f * a);
        }
    }
    __syncthreads();

    // ---- phase C: rank-5 projection -> initial w (float4 loads of w2) ----
    {
        float invC = g_P.invCmax;
        float y[5] = {0, 0, 0, 0, 0};
        for (int e = 0; e < 8; e++) {
            int i = tid + e * 512;
            float s = fixs(scores[b * NN + i]);
            float bb[16];
            float rowacc = 0.0f;
#pragma unroll
            for (int c = 0; c < KK; c++) {
                float sg = g_sig[(b * KK + c) * NN + i];
                float ds = s - (float)(KK - c);
                bb[c] = ds * ds * invC + EPSV * __logf(sg) - lc[c];
                rowacc += sg * sinv[c];
            }
            float last = (1.0f - rowacc) * MUV;
            last = fminf(fmaxf(last, SMALLV), 1.0f - SMALLV);
            bb[15] = s * s * invC + EPSV * __logf(last);
#pragma unroll
            for (int r = 0; r < 5; r++) {
                const float4* wv = reinterpret_cast<const float4*>(w2 + r * 65536 + i * 16);
                float4 a0 = wv[0], a1 = wv[1], a2 = wv[2], a3 = wv[3];
                float acc = bb[0] * a0.x + bb[1] * a0.y + bb[2] * a0.z + bb[3] * a0.w;
                acc += bb[4] * a1.x + bb[5] * a1.y + bb[6] * a1.z + bb[7] * a1.w;
                acc += bb[8] * a2.x + bb[9] * a2.y + bb[10] * a2.z + bb[11] * a2.w;
                acc += bb[12] * a3.x + bb[13] * a3.y + bb[14] * a3.z + bb[15] * a3.w;
                y[r] += acc;
            }
        }
#pragma unroll
        for (int r = 0; r < 5; r++) y[r] = warp_sum(y[r]);
        if (!lane) {
#pragma unroll
            for (int r = 0; r < 5; r++) sy[wid][r] = y[r];
        }
        __syncthreads();
        if (tid < 5) {
            float a = 0.0f;
            for (int w = 0; w < 16; w++) a += sy[w][tid];
            yf[tid] = a;
        }
        __syncthreads();
        if (tid < KK) {
            float g = 0.0f;
#pragma unroll
            for (int r = 0; r < 5; r++) g += yf[r] * w1[(NN + tid) * 5 + r];
            gg[tid] = g;
        }
        __syncthreads();
        if (tid < 16) {
            int m = tid;
            float w = (m == 0) ? 1.0f
                     : __expf(10.0f * gg[KK - m] - g_P.alpha * (float)(m * m));
            g_w[b * 16 + m] = w;
        }
    }
}

// ---------------- fused main: 200-iter Sinkhorn + output + norm ----------------
// 512 threads, 4 packed pairs per thread; X/X2/X4/X8 stored (x^12 synthesized)
__global__ __launch_bounds__(512, 1) void kMain(const float* __restrict__ scores,
                                                float* __restrict__ out) {
    int b = blockIdx.x, tid = threadIdx.x, lane = tid & 31, wid = tid >> 5;  // 16 warps
    __shared__ float sS[2][16][16];
    __shared__ float sinv[KK];
    float c2 = g_P.c_exp2;
    const float2* sc2 = reinterpret_cast<const float2*>(scores + b * NN);
    float2* t2out = reinterpret_cast<float2*>(g_t + b * NN);

    ull X[4], X2[4], X4[4], X8[4];
#pragma unroll
    for (int p = 0; p < 4; p++) {
        float2 s = sc2[tid + p * 512];
        float xlo = exp2f(c2 * fixs(s.x));
        float xhi = exp2f(c2 * fixs(s.y));
        ull x = pk2(xlo, xhi);
        X[p] = x;
        X2[p] = mul2(x, x);
        X4[p] = mul2(X2[p], X2[p]);
        X8[p] = mul2(X4[p], X4[p]);
    }
    ull W[16];
#pragma unroll
    for (int m = 0; m < 16; m++) { float v = g_w[b * 16 + m]; W[m] = pk2(v, v); }

    for (int it = 0; it < NITER; it++) {
        ull S[16];
#pragma unroll
        for (int m = 0; m < 16; m++) S[m] = 0ull;
#pragma unroll
        for (int p = 0; p < 4; p++) {
            ull x2 = X2[p];
            // H = A(x^2) + x*B(x^2)
            ull A = W[14], B = W[15];
#pragma unroll
            for (int j = 6; j >= 1; j--) {
                A = fma2(A, x2, W[2 * j]);
                B = fma2(B, x2, W[2 * j + 1]);
            }
            A = fma2(A, x2, W[0]);
            B = fma2(B, x2, W[1]);
            ull H = fma2(X[p], B, A);
            float hlo, hhi; upk2(hlo, hhi, H);
            float tlo = MUV * rcpa(hlo);
            float thi = MUV * rcpa(hhi);
            if (it == NITER - 1) t2out[tid + p * 512] = make_float2(tlo, thi);
            ull t0 = pk2(tlo, thi);
            ull t1 = mul2(t0, X[p]);
            ull t2 = mul2(t0, x2);
            ull t3 = mul2(t1, x2);
            ull u0 = mul2(t0, X4[p]);
            ull u1 = mul2(t1, X4[p]);
            ull u2 = mul2(t2, X4[p]);
            ull u3 = mul2(t3, X4[p]);
            S[0] = add2(S[0], t0);  S[1] = add2(S[1], t1);
            S[2] = add2(S[2], t2);  S[3] = add2(S[3], t3);
            S[4] = add2(S[4], u0);  S[5] = add2(S[5], u1);
            S[6] = add2(S[6], u2);  S[7] = add2(S[7], u3);
            S[8]  = fma2(t0, X8[p], S[8]);
            S[9]  = fma2(t1, X8[p], S[9]);
            S[10] = fma2(t2, X8[p], S[10]);
            S[11] = fma2(t3, X8[p], S[11]);
            S[12] = fma2(u0, X8[p], S[12]);
            S[13] = fma2(u1, X8[p], S[13]);
            S[14] = fma2(u2, X8[p], S[14]);
            S[15] = fma2(u3, X8[p], S[15]);
        }
        // pairwise halves
        float v[16];
#pragma unroll
        for (int m = 0; m < 16; m++) { float lo, hi; upk2(lo, hi, S[m]); v[m] = lo + hi; }
        // index-matched butterfly: value m's bit j follows lane bit j
        float u8[8];
#pragma unroll
        for (int q = 0; q < 8; q++) {
            float keep = (lane & 1) ? v[2 * q + 1] : v[2 * q];
            float send = (lane & 1) ? v[2 * q] : v[2 * q + 1];
            u8[q] = keep + __shfl_xor_sync(0xffffffffu, send, 1);
        }
        float u4[4];
#pragma unroll
        for (int q = 0; q < 4; q++) {
            float keep = (lane & 2) ? u8[2 * q + 1] : u8[2 * q];
            float send = (lane & 2) ? u8[2 * q] : u8[2 * q + 1];
            u4[q] = keep + __shfl_xor_sync(0xffffffffu, send, 2);
        }
        float u2v[2];
#pragma unroll
        for (int q = 0; q < 2; q++) {
            float keep = (lane & 4) ? u4[2 * q + 1] : u4[2 * q];
            float send = (lane & 4) ? u4[2 * q] : u4[2 * q + 1];
            u2v[q] = keep + __shfl_xor_sync(0xffffffffu, send, 4);
        }
        float k1 = (lane & 8) ? u2v[1] : u2v[0];
        float s1 = (lane & 8) ? u2v[0] : u2v[1];
        float u1f = k1 + __shfl_xor_sync(0xffffffffu, s1, 8);
        float tot = u1f + __shfl_xor_sync(0xffffffffu, u1f, 16);
        // tot = warp total for index m = lane & 15
        int par = it & 1;
        if (lane < 16) sS[par][wid][lane] = tot;
        __syncthreads();
        int m = lane & 15;
        float a = 0.0f;
#pragma unroll
        for (int q = 0; q < 16; q++) a += sS[par][q][m];
        float nu = (m == 0) ? NU0 : MUV;
        float wv = nu * rcpa(a);
#pragma unroll
        for (int m2 = 0; m2 < 16; m2++) {
            float x = __shfl_sync(0xffffffffu, wv, m2);
            W[m2] = pk2(x, x);
        }
    }

    // ---- epilogue: Gamma, output A, norm ----
    if (tid < KK) sinv[tid] = 1.0f / g_colsum[b * KK + tid];
    __syncthreads();
    float nacc = 0.0f;
#pragma unroll
    for (int p = 0; p < 4; p++) {
        float2 tv = t2out[tid + p * 512];
        ull t0 = pk2(tv.x, tv.y);
        ull t1 = mul2(t0, X[p]);
        ull t2 = mul2(t0, X2[p]);
        ull t3 = mul2(t1, X2[p]);
        ull u0 = mul2(t0, X4[p]);
        ull u1 = mul2(t1, X4[p]);
        ull u2 = mul2(t2, X4[p]);
        ull u3 = mul2(t3, X4[p]);
        ull gp[16];
        gp[0] = mul2(t0, W[0]);  gp[1] = mul2(t1, W[1]);
        gp[2] = mul2(t2, W[2]);  gp[3] = mul2(t3, W[3]);
        gp[4] = mul2(u0, W[4]);  gp[5] = mul2(u1, W[5]);
        gp[6] = mul2(u2, W[6]);  gp[7] = mul2(u3, W[7]);
        gp[8]  = mul2(mul2(t0, X8[p]), W[8]);
        gp[9]  = mul2(mul2(t1, X8[p]), W[9]);
        gp[10] = mul2(mul2(t2, X8[p]), W[10]);
        gp[11] = mul2(mul2(t3, X8[p]), W[11]);
        gp[12] = mul2(mul2(u0, X8[p]), W[12]);
        gp[13] = mul2(mul2(u1, X8[p]), W[13]);
        gp[14] = mul2(mul2(u2, X8[p]), W[14]);
        gp[15] = mul2(mul2(u3, X8[p]), W[15]);
        float glo[16], ghi[16];
#pragma unroll
        for (int m = 0; m < 16; m++) upk2(glo[m], ghi[m], gp[m]);
        int e0 = 2 * (tid + p * 512);
        float* Ao0 = out + ((size_t)(b * NN + e0)) * 15;
        float* Ao1 = Ao0 + 15;
#pragma unroll
        for (int c = 0; c < KK; c++) {
            Ao0[c] = 4096.0f * glo[15 - c];
            Ao1[c] = 4096.0f * ghi[15 - c];
        }
        float racc0 = 0.0f, racc1 = 0.0f;
#pragma unroll
        for (int c = 0; c < KK; c++) {
            const float2 sg2 = *reinterpret_cast<const float2*>(
                &g_sig[(b * KK + c) * NN + e0]);
            float sn0 = sg2.x * sinv[c];
            float sn1 = sg2.y * sinv[c];
            racc0 += sn0; racc1 += sn1;
            float d0 = glo[15 - c] - sn0 * MUV;
            float d1 = ghi[15 - c] - sn1 * MUV;
            nacc += d0 * d0 + d1 * d1;
        }
        float l0 = fminf(fmaxf((1.0f - racc0) * MUV, SMALLV), 1.0f - SMALLV);
        float l1 = fminf(fmaxf((1.0f - racc1) * MUV, SMALLV), 1.0f - SMALLV);
        float d0 = glo[0] - l0, d1 = ghi[0] - l1;
        nacc += d0 * d0 + d1 * d1;
    }
    nacc = warp_sum(nacc);
    __shared__ float snrm[16];
    if (!lane) snrm[wid] = nacc;
    __syncthreads();
    if (tid == 0) {
        float a = 0.0f;
        for (int q = 0; q < 16; q++) a += snrm[q];
        atomicAdd(&g_norm, (double)a);
    }
}

__global__ void kFin(float* __restrict__ out, int out_size) {
    if (threadIdx.x == 0) out[out_size - 1] = sqrtf((float)g_norm);
}

extern "C" void kernel_launch(void* const* d_in, const int* in_sizes, int n_in,
                              void* d_out, int out_size) {
    const float* scores = (const float*)d_in[0];
    const float* tau    = (const float*)d_in[1];
    const float* w1     = (const float*)d_in[2];
    const float* w2     = (const float*)d_in[3];
    float* out = (float*)d_out;
    kA1<<<256, 256>>>(scores);
    kA2<<<1, 256>>>(tau);
    kPre<<<NB, 512>>>(scores, w1, w2);
    kMain<<<NB, 512>>>(scores, out);
    kFin<<<1, 1>>>(out, out_size);
}

// round 7
// speedup vs baseline: 1.0292x; 1.0292x over previous
#include <cuda_runtime.h>
#include <math.h>

#define NB 128
#define NN 4096
#define KK 15
#define EPSV 0.1f
#define SMALLV 1e-20f
#define MUV 2.44140625e-4f   /* 1/4096 */
#define NU0 (4081.0f/4096.0f)
#define NITER 200

typedef unsigned long long ull;

// ---------------- device scratch (static, no allocation) ----------------
__device__ float g_sig[NB * KK * NN];   // sigmoid+SMALL, layout [b][j][i]
__device__ float g_colsum[NB * KK];     // per-(b,j) column sums of sig
__device__ float g_w[NB * 16];          // initial Sinkhorn state w_m
__device__ float g_t[NB * NN];          // t_i from final iteration
__device__ float g_mx[256], g_mn[256];
__device__ int   g_fl[256];
__device__ double g_norm;

struct Par { float filled, invCmax, alpha, inv_tau, c_exp2; };
__device__ Par g_P;

// ---------------- helpers ----------------
__device__ __forceinline__ float warp_sum(float v) {
#pragma unroll
    for (int o = 16; o > 0; o >>= 1) v += __shfl_xor_sync(0xffffffffu, v, o);
    return v;
}
__device__ __forceinline__ float warp_max(float v) {
#pragma unroll
    for (int o = 16; o > 0; o >>= 1) v = fmaxf(v, __shfl_xor_sync(0xffffffffu, v, o));
    return v;
}
__device__ __forceinline__ float warp_min(float v) {
#pragma unroll
    for (int o = 16; o > 0; o >>= 1) v = fminf(v, __shfl_xor_sync(0xffffffffu, v, o));
    return v;
}
__device__ __forceinline__ int warp_or(int v) {
#pragma unroll
    for (int o = 16; o > 0; o >>= 1) v |= __shfl_xor_sync(0xffffffffu, v, o);
    return v;
}
__device__ __forceinline__ float rcpa(float x) {
    float y; asm("rcp.approx.f32 %0, %1;" : "=f"(y) : "f"(x)); return y;
}
__device__ __forceinline__ float fixs(float s) {
    return (isinf(s) && s < 0.0f) ? g_P.filled : s;
}

// ---------------- packed f32x2 (sm_103a) ----------------
__device__ __forceinline__ ull pk2(float lo, float hi) {
    ull r; asm("mov.b64 %0, {%1,%2};" : "=l"(r) : "f"(lo), "f"(hi)); return r;
}
__device__ __forceinline__ void upk2(float& lo, float& hi, ull v) {
    asm("mov.b64 {%0,%1}, %2;" : "=f"(lo), "=f"(hi) : "l"(v));
}
__device__ __forceinline__ ull fma2(ull a, ull b, ull c) {
    ull d; asm("fma.rn.f32x2 %0, %1, %2, %3;" : "=l"(d) : "l"(a), "l"(b), "l"(c)); return d;
}
__device__ __forceinline__ ull mul2(ull a, ull b) {
    ull d; asm("mul.rn.f32x2 %0, %1, %2;" : "=l"(d) : "l"(a), "l"(b)); return d;
}
__device__ __forceinline__ ull add2(ull a, ull b) {
    ull d; asm("add.rn.f32x2 %0, %1, %2;" : "=l"(d) : "l"(a), "l"(b)); return d;
}
// volatile LDS.64 of a duplicated-packed W coefficient (prevents reg-hoisting)
__device__ __forceinline__ ull ldsW(unsigned addr) {
    ull v; asm volatile("ld.shared.b64 %0, [%1];" : "=l"(v) : "r"(addr)); return v;
}
__device__ __forceinline__ void stsW(unsigned addr, ull v) {
    asm volatile("st.shared.b64 [%0], %1;" :: "r"(addr), "l"(v));
}

// ---------------- A1: global min/max partials ----------------
__global__ void kA1(const float* __restrict__ scores) {
    int tid = threadIdx.x;
    int base = blockIdx.x * 2048 + tid * 8;
    const float4* p4 = reinterpret_cast<const float4*>(scores + base);
    float4 a = p4[0], b = p4[1];
    float vs[8] = {a.x, a.y, a.z, a.w, b.x, b.y, b.z, b.w};
    float mx = -3.4e38f, mn = 3.4e38f; int fl = 0;
#pragma unroll
    for (int t = 0; t < 8; t++) {
        float x = vs[t];
        if (isinf(x) && x < 0.0f) fl = 1;
        else mn = fminf(mn, x);
        mx = fmaxf(mx, x);
    }
    mx = warp_max(mx); mn = warp_min(mn); fl = warp_or(fl);
    __shared__ float smx[8], smn[8]; __shared__ int sfl[8];
    int lane = tid & 31, wid = tid >> 5;
    if (!lane) { smx[wid] = mx; smn[wid] = mn; sfl[wid] = fl; }
    __syncthreads();
    if (tid == 0) {
        for (int w = 1; w < 8; w++) { mx = fmaxf(mx, smx[w]); mn = fminf(mn, smn[w]); fl |= sfl[w]; }
        g_mx[blockIdx.x] = mx; g_mn[blockIdx.x] = mn; g_fl[blockIdx.x] = fl;
    }
}

// ---------------- A2: finalize scalar params ----------------
__global__ void kA2(const float* __restrict__ tau) {
    int tid = threadIdx.x, lane = tid & 31, wid = tid >> 5;
    float mx = g_mx[tid], mn = g_mn[tid]; int fl = g_fl[tid];
    mx = warp_max(mx); mn = warp_min(mn); fl = warp_or(fl);
    __shared__ float smx[8], smn[8]; __shared__ int sfl[8];
    if (!lane) { smx[wid] = mx; smn[wid] = mn; sfl[wid] = fl; }
    __syncthreads();
    if (tid == 0) {
        for (int w = 1; w < 8; w++) { mx = fmaxf(mx, smx[w]); mn = fminf(mn, smn[w]); fl |= sfl[w]; }
        float filled = mn - (mx - mn);
        float lo = fl ? filled : mn;
        float d1 = lo - 15.0f, d2 = mx - 15.0f;
        float Cmax = fmaxf(fmaxf(lo * lo, d1 * d1), fmaxf(mx * mx, d2 * d2));
        float invC = 1.0f / Cmax;
        Par P;
        P.filled = filled; P.invCmax = invC; P.alpha = 10.0f * invC;
        P.inv_tau = 1.0f / tau[0];
        P.c_exp2 = 2.0f * (10.0f * invC) * 1.4426950408889634f;
        g_P = P;
        g_norm = 0.0;
    }
}

// ---------------- fused prepass: top-15, sigmoids+colsums, rank-5 warm start ----------------
__global__ __launch_bounds__(512) void kPre(const float* __restrict__ scores,
                                            const float* __restrict__ w1,
                                            const float* __restrict__ w2) {
    int b = blockIdx.x, tid = threadIdx.x, lane = tid & 31, wid = tid >> 5;
    __shared__ float stv[KK];
    __shared__ float swm[16];
    __shared__ float sbc;
    __shared__ int claim;
    __shared__ float scs[16][KK];
    __shared__ float sinv[KK], lc[KK];
    __shared__ float sy[16][5];
    __shared__ float yf[5];
    __shared__ float gg[KK];

    // ---- phase A: top-15 via 15 masked argmax rounds ----
    {
        const float4* p4 = reinterpret_cast<const float4*>(scores + b * NN) + tid * 2;
        float4 a = p4[0], c4 = p4[1];
        float v[8] = {a.x, a.y, a.z, a.w, c4.x, c4.y, c4.z, c4.w};
#pragma unroll
        for (int e = 0; e < 8; e++) v[e] = fixs(v[e]);
        for (int r = 0; r < KK; r++) {
            float lm = v[0];
#pragma unroll
            for (int e = 1; e < 8; e++) lm = fmaxf(lm, v[e]);
            lm = warp_max(lm);
            if (!lane) swm[wid] = lm;
            __syncthreads();
            if (tid == 0) {
                float m = swm[0];
                for (int w = 1; w < 16; w++) m = fmaxf(m, swm[w]);
                sbc = m; claim = 0;
                stv[r] = m;
            }
            __syncthreads();
            float m = sbc;
            int idx = -1;
#pragma unroll
            for (int e = 0; e < 8; e++) if (idx < 0 && v[e] == m) idx = e;
            if (idx >= 0) {
                int old = atomicAdd(&claim, 1);
                if (old == 0) v[idx] = -3.4e38f;
            }
        }
    }
    __syncthreads();

    // ---- phase B: sigmoids + column sums ----
    {
        float itau = g_P.inv_tau;
        float cs[KK];
#pragma unroll
        for (int j = 0; j < KK; j++) cs[j] = 0.0f;
        for (int e = 0; e < 8; e++) {
            int i = tid + e * 512;
            float s = fixs(scores[b * NN + i]);
#pragma unroll
            for (int j = 0; j < KK; j++) {
                float d = fabsf(stv[j] - s) * itau;
                float ex = __expf(d);
                float sg = rcpa(1.0f + ex) + SMALLV;
                g_sig[(b * KK + j) * NN + i] = sg;
                cs[j] += sg;
            }
        }
#pragma unroll
        for (int j = 0; j < KK; j++) cs[j] = warp_sum(cs[j]);
        if (!lane) {
#pragma unroll
            for (int j = 0; j < KK; j++) scs[wid][j] = cs[j];
        }
        __syncthreads();
        if (tid < KK) {
            float a = 0.0f;
            for (int w = 0; w < 16; w++) a += scs[w][tid];
            g_colsum[b * KK + tid] = a;
            sinv[tid] = 1.0f / a;
            lc[tid] = EPSV * __logf(4096.0f * a);
        }
    }
    __syncthreads();

    // ---- phase C: rank-5 projection -> initial w (float4 loads of w2) ----
    {
        float invC = g_P.invCmax;
        float y[5] = {0, 0, 0, 0, 0};
        for (int e = 0; e < 8; e++) {
            int i = tid + e * 512;
            float s = fixs(scores[b * NN + i]);
            float bb[16];
            float rowacc = 0.0f;
#pragma unroll
            for (int c = 0; c < KK; c++) {
                float sg = g_sig[(b * KK + c) * NN + i];
                float ds = s - (float)(KK - c);
                bb[c] = ds * ds * invC + EPSV * __logf(sg) - lc[c];
                rowacc += sg * sinv[c];
            }
            float last = (1.0f - rowacc) * MUV;
            last = fminf(fmaxf(last, SMALLV), 1.0f - SMALLV);
            bb[15] = s * s * invC + EPSV * __logf(last);
#pragma unroll
            for (int r = 0; r < 5; r++) {
                const float4* wv = reinterpret_cast<const float4*>(w2 + r * 65536 + i * 16);
                float4 a0 = wv[0], a1 = wv[1], a2 = wv[2], a3 = wv[3];
                float acc = bb[0] * a0.x + bb[1] * a0.y + bb[2] * a0.z + bb[3] * a0.w;
                acc += bb[4] * a1.x + bb[5] * a1.y + bb[6] * a1.z + bb[7] * a1.w;
                acc += bb[8] * a2.x + bb[9] * a2.y + bb[10] * a2.z + bb[11] * a2.w;
                acc += bb[12] * a3.x + bb[13] * a3.y + bb[14] * a3.z + bb[15] * a3.w;
                y[r] += acc;
            }
        }
#pragma unroll
        for (int r = 0; r < 5; r++) y[r] = warp_sum(y[r]);
        if (!lane) {
#pragma unroll
            for (int r = 0; r < 5; r++) sy[wid][r] = y[r];
        }
        __syncthreads();
        if (tid < 5) {
            float a = 0.0f;
            for (int w = 0; w < 16; w++) a += sy[w][tid];
            yf[tid] = a;
        }
        __syncthreads();
        if (tid < KK) {
            float g = 0.0f;
#pragma unroll
            for (int r = 0; r < 5; r++) g += yf[r] * w1[(NN + tid) * 5 + r];
            gg[tid] = g;
        }
        __syncthreads();
        if (tid < 16) {
            int m = tid;
            float w = (m == 0) ? 1.0f
                     : __expf(10.0f * gg[KK - m] - g_P.alpha * (float)(m * m));
            g_w[b * 16 + m] = w;
        }
    }
}

// ---------------- fused main: 200-iter Sinkhorn + output + norm ----------------
// 512 threads, 4 packed pairs/thread. W lives in per-warp SMEM slots (volatile
// LDS.64) so it costs 0 registers in the loop -> no spills at the 128-reg cap.
__global__ __launch_bounds__(512, 1) void kMain(const float* __restrict__ scores,
                                                float* __restrict__ out) {
    int b = blockIdx.x, tid = threadIdx.x, lane = tid & 31, wid = tid >> 5;  // 16 warps
    __shared__ float sS[2][16][16];
    __shared__ ull sWd[16][16];     // per-warp duplicated-packed W
    __shared__ float sinv[KK];
    float c2 = g_P.c_exp2;
    const float2* sc2 = reinterpret_cast<const float2*>(scores + b * NN);
    float2* t2out = reinterpret_cast<float2*>(g_t + b * NN);

    unsigned wbase;
    {
        void* p = &sWd[wid][0];
        asm("{ .reg .u64 t; cvta.to.shared.u64 t, %1; cvt.u32.u64 %0, t; }"
            : "=r"(wbase) : "l"(p));
    }

    ull X[4], X2[4], X4[4], X8[4];
#pragma unroll
    for (int p = 0; p < 4; p++) {
        float2 s = sc2[tid + p * 512];
        float xlo = exp2f(c2 * fixs(s.x));
        float xhi = exp2f(c2 * fixs(s.y));
        ull x = pk2(xlo, xhi);
        X[p] = x;
        X2[p] = mul2(x, x);
        X4[p] = mul2(X2[p], X2[p]);
        X8[p] = mul2(X4[p], X4[p]);
    }
    // each warp initializes its own W slot (no cross-warp access -> syncwarp only)
    if (lane < 16) {
        float v = g_w[b * 16 + lane];
        stsW(wbase + lane * 8, pk2(v, v));
    }
    __syncwarp();

    for (int it = 0; it < NITER; it++) {
        ull S[16];
#pragma unroll
        for (int m = 0; m < 16; m++) S[m] = 0ull;
#pragma unroll
        for (int p = 0; p < 4; p++) {
            ull x2 = X2[p];
            // H = A(x^2) + x*B(x^2), coefficients streamed from SMEM
            ull A = ldsW(wbase + 14 * 8);
            ull B = ldsW(wbase + 15 * 8);
#pragma unroll
            for (int j = 6; j >= 0; j--) {
                A = fma2(A, x2, ldsW(wbase + (2 * j) * 8));
                B = fma2(B, x2, ldsW(wbase + (2 * j + 1) * 8));
            }
            ull H = fma2(X[p], B, A);
            float hlo, hhi; upk2(hlo, hhi, H);
            float tlo = MUV * rcpa(hlo);
            float thi = MUV * rcpa(hhi);
            if (it == NITER - 1) t2out[tid + p * 512] = make_float2(tlo, thi);
            ull t0 = pk2(tlo, thi);
            ull t1 = mul2(t0, X[p]);
            ull t2 = mul2(t0, x2);
            ull t3 = mul2(t1, x2);
            ull u0 = mul2(t0, X4[p]);
            ull u1 = mul2(t1, X4[p]);
            ull u2 = mul2(t2, X4[p]);
            ull u3 = mul2(t3, X4[p]);
            S[0] = add2(S[0], t0);  S[1] = add2(S[1], t1);
            S[2] = add2(S[2], t2);  S[3] = add2(S[3], t3);
            S[4] = add2(S[4], u0);  S[5] = add2(S[5], u1);
            S[6] = add2(S[6], u2);  S[7] = add2(S[7], u3);
            S[8]  = fma2(t0, X8[p], S[8]);
            S[9]  = fma2(t1, X8[p], S[9]);
            S[10] = fma2(t2, X8[p], S[10]);
            S[11] = fma2(t3, X8[p], S[11]);
            S[12] = fma2(u0, X8[p], S[12]);
            S[13] = fma2(u1, X8[p], S[13]);
            S[14] = fma2(u2, X8[p], S[14]);
            S[15] = fma2(u3, X8[p], S[15]);
        }
        // pairwise halves
        float v[16];
#pragma unroll
        for (int m = 0; m < 16; m++) { float lo, hi; upk2(lo, hi, S[m]); v[m] = lo + hi; }
        // index-matched butterfly: value m's bit j follows lane bit j
        float u8[8];
#pragma unroll
        for (int q = 0; q < 8; q++) {
            float keep = (lane & 1) ? v[2 * q + 1] : v[2 * q];
            float send = (lane & 1) ? v[2 * q] : v[2 * q + 1];
            u8[q] = keep + __shfl_xor_sync(0xffffffffu, send, 1);
        }
        float u4[4];
#pragma unroll
        for (int q = 0; q < 4; q++) {
            float keep = (lane & 2) ? u8[2 * q + 1] : u8[2 * q];
            float send = (lane & 2) ? u8[2 * q] : u8[2 * q + 1];
            u4[q] = keep + __shfl_xor_sync(0xffffffffu, send, 2);
        }
        float u2v[2];
#pragma unroll
        for (int q = 0; q < 2; q++) {
            float keep = (lane & 4) ? u4[2 * q + 1] : u4[2 * q];
            float send = (lane & 4) ? u4[2 * q] : u4[2 * q + 1];
            u2v[q] = keep + __shfl_xor_sync(0xffffffffu, send, 4);
        }
        float k1 = (lane & 8) ? u2v[1] : u2v[0];
        float s1 = (lane & 8) ? u2v[0] : u2v[1];
        float u1f = k1 + __shfl_xor_sync(0xffffffffu, s1, 8);
        float tot = u1f + __shfl_xor_sync(0xffffffffu, u1f, 16);
        // tot = warp total for index m = lane & 15
        int par = it & 1;
        if (lane < 16) sS[par][wid][lane] = tot;
        __syncthreads();
        int m = lane & 15;
        float a = 0.0f;
#pragma unroll
        for (int q = 0; q < 16; q++) a += sS[par][q][m];
        float nu = (m == 0) ? NU0 : MUV;
        float wv = nu * rcpa(a);
        if (lane < 16) stsW(wbase + lane * 8, pk2(wv, wv));
        __syncwarp();
    }

    // ---- epilogue: Gamma, output A, norm (column-at-a-time, low pressure) ----
    if (tid < KK) sinv[tid] = 1.0f / g_colsum[b * KK + tid];
    __syncthreads();
    float nacc = 0.0f;
#pragma unroll
    for (int p = 0; p < 4; p++) {
        float2 tv = t2out[tid + p * 512];
        ull t0 = pk2(tv.x, tv.y);
        ull t1 = mul2(t0, X[p]);
        ull t2 = mul2(t0, X2[p]);
        ull t3 = mul2(t1, X2[p]);
        ull u0 = mul2(t0, X4[p]);
        ull u1 = mul2(t1, X4[p]);
        ull u2 = mul2(t2, X4[p]);
        ull u3 = mul2(t3, X4[p]);
        int e0 = 2 * (tid + p * 512);
        float* Ao0 = out + ((size_t)(b * NN + e0)) * 15;
        float* Ao1 = Ao0 + 15;
        float racc0 = 0.0f, racc1 = 0.0f;
        float g0lo = 0.0f, g0hi = 0.0f;  // gam[0] saved for the last column
#pragma unroll
        for (int m = 0; m < 16; m++) {
            // base factor for power m
            ull base;
            if (m == 0) base = t0; else if (m == 1) base = t1;
            else if (m == 2) base = t2; else if (m == 3) base = t3;
            else if (m == 4) base = u0; else if (m == 5) base = u1;
            else if (m == 6) base = u2; else if (m == 7) base = u3;
            else if (m == 8)  base = mul2(t0, X8[p]);
            else if (m == 9)  base = mul2(t1, X8[p]);
            else if (m == 10) base = mul2(t2, X8[p]);
            else if (m == 11) base = mul2(t3, X8[p]);
            else if (m == 12) base = mul2(u0, X8[p]);
            else if (m == 13) base = mul2(u1, X8[p]);
            else if (m == 14) base = mul2(u2, X8[p]);
            else              base = mul2(u3, X8[p]);
            ull g = mul2(base, sWd[wid][m]);   // plain LDS, epilogue only
            float glo, ghi; upk2(glo, ghi, g);
            if (m == 0) { g0lo = glo; g0hi = ghi; }
            else {
                int c = 15 - m;   // output column
                Ao0[c] = 4096.0f * glo;
                Ao1[c] = 4096.0f * ghi;
                const float2 sg2 = *reinterpret_cast<const float2*>(
                    &g_sig[(b * KK + c) * NN + e0]);
                float sn0 = sg2.x * sinv[c];
                float sn1 = sg2.y * sinv[c];
                racc0 += sn0; racc1 += sn1;
                float d0 = glo - sn0 * MUV;
                float d1 = ghi - sn1 * MUV;
                nacc += d0 * d0 + d1 * d1;
            }
        }
        float l0 = fminf(fmaxf((1.0f - racc0) * MUV, SMALLV), 1.0f - SMALLV);
        float l1 = fminf(fmaxf((1.0f - racc1) * MUV, SMALLV), 1.0f - SMALLV);
        float d0 = g0lo - l0, d1 = g0hi - l1;
        nacc += d0 * d0 + d1 * d1;
    }
    nacc = warp_sum(nacc);
    __shared__ float snrm[16];
    if (!lane) snrm[wid] = nacc;
    __syncthreads();
    if (tid == 0) {
        float a = 0.0f;
        for (int q = 0; q < 16; q++) a += snrm[q];
        atomicAdd(&g_norm, (double)a);
    }
}

__global__ void kFin(float* __restrict__ out, int out_size) {
    if (threadIdx.x == 0) out[out_size - 1] = sqrtf((float)g_norm);
}

extern "C" void kernel_launch(void* const* d_in, const int* in_sizes, int n_in,
                              void* d_out, int out_size) {
    const float* scores = (const float*)d_in[0];
    const float* tau    = (const float*)d_in[1];
    const float* w1     = (const float*)d_in[2];
    const float* w2     = (const float*)d_in[3];
    float* out = (float*)d_out;
    kA1<<<256, 256>>>(scores);
    kA2<<<1, 256>>>(tau);
    kPre<<<NB, 512>>>(scores, w1, w2);
    kMain<<<NB, 512>>>(scores, out);
    kFin<<<1, 1>>>(out, out_size);
}

// round 8
// speedup vs baseline: 3.6077x; 3.5053x over previous
#include <cuda_runtime.h>
#include <math.h>

#define NB 128
#define NN 4096
#define KK 15
#define EPSV 0.1f
#define SMALLV 1e-20f
#define MUV 2.44140625e-4f   /* 1/4096 */
#define NU0 (4081.0f/4096.0f)
#define NITER 200
#define CONVTOL 1e-6f

typedef unsigned long long ull;

// ---------------- device scratch (static, no allocation) ----------------
__device__ float g_sig[NB * KK * NN];   // sigmoid+SMALL, layout [b][j][i]
__device__ float g_colsum[NB * KK];     // per-(b,j) column sums of sig
__device__ float g_w[NB * 16];          // initial Sinkhorn state w_m
__device__ float g_mx[256], g_mn[256];
__device__ int   g_fl[256];
__device__ double g_norm;

struct Par { float filled, invCmax, alpha, inv_tau, c_exp2; };
__device__ Par g_P;

// ---------------- helpers ----------------
__device__ __forceinline__ float warp_sum(float v) {
#pragma unroll
    for (int o = 16; o > 0; o >>= 1) v += __shfl_xor_sync(0xffffffffu, v, o);
    return v;
}
__device__ __forceinline__ float warp_max(float v) {
#pragma unroll
    for (int o = 16; o > 0; o >>= 1) v = fmaxf(v, __shfl_xor_sync(0xffffffffu, v, o));
    return v;
}
__device__ __forceinline__ float warp_min(float v) {
#pragma unroll
    for (int o = 16; o > 0; o >>= 1) v = fminf(v, __shfl_xor_sync(0xffffffffu, v, o));
    return v;
}
__device__ __forceinline__ int warp_or(int v) {
#pragma unroll
    for (int o = 16; o > 0; o >>= 1) v |= __shfl_xor_sync(0xffffffffu, v, o);
    return v;
}
__device__ __forceinline__ float rcpa(float x) {
    float y; asm("rcp.approx.f32 %0, %1;" : "=f"(y) : "f"(x)); return y;
}
__device__ __forceinline__ float fixs(float s) {
    return (isinf(s) && s < 0.0f) ? g_P.filled : s;
}

// ---------------- packed f32x2 (sm_103a) ----------------
__device__ __forceinline__ ull pk2(float lo, float hi) {
    ull r; asm("mov.b64 %0, {%1,%2};" : "=l"(r) : "f"(lo), "f"(hi)); return r;
}
__device__ __forceinline__ void upk2(float& lo, float& hi, ull v) {
    asm("mov.b64 {%0,%1}, %2;" : "=f"(lo), "=f"(hi) : "l"(v));
}
__device__ __forceinline__ ull fma2(ull a, ull b, ull c) {
    ull d; asm("fma.rn.f32x2 %0, %1, %2, %3;" : "=l"(d) : "l"(a), "l"(b), "l"(c)); return d;
}
__device__ __forceinline__ ull mul2(ull a, ull b) {
    ull d; asm("mul.rn.f32x2 %0, %1, %2;" : "=l"(d) : "l"(a), "l"(b)); return d;
}
__device__ __forceinline__ ull add2(ull a, ull b) {
    ull d; asm("add.rn.f32x2 %0, %1, %2;" : "=l"(d) : "l"(a), "l"(b)); return d;
}

// ---------------- A1: global min/max partials ----------------
__global__ void kA1(const float* __restrict__ scores) {
    int tid = threadIdx.x;
    int base = blockIdx.x * 2048 + tid * 8;
    const float4* p4 = reinterpret_cast<const float4*>(scores + base);
    float4 a = p4[0], b = p4[1];
    float vs[8] = {a.x, a.y, a.z, a.w, b.x, b.y, b.z, b.w};
    float mx = -3.4e38f, mn = 3.4e38f; int fl = 0;
#pragma unroll
    for (int t = 0; t < 8; t++) {
        float x = vs[t];
        if (isinf(x) && x < 0.0f) fl = 1;
        else mn = fminf(mn, x);
        mx = fmaxf(mx, x);
    }
    mx = warp_max(mx); mn = warp_min(mn); fl = warp_or(fl);
    __shared__ float smx[8], smn[8]; __shared__ int sfl[8];
    int lane = tid & 31, wid = tid >> 5;
    if (!lane) { smx[wid] = mx; smn[wid] = mn; sfl[wid] = fl; }
    __syncthreads();
    if (tid == 0) {
        for (int w = 1; w < 8; w++) { mx = fmaxf(mx, smx[w]); mn = fminf(mn, smn[w]); fl |= sfl[w]; }
        g_mx[blockIdx.x] = mx; g_mn[blockIdx.x] = mn; g_fl[blockIdx.x] = fl;
    }
}

// ---------------- A2: finalize scalar params ----------------
__global__ void kA2(const float* __restrict__ tau) {
    int tid = threadIdx.x, lane = tid & 31, wid = tid >> 5;
    float mx = g_mx[tid], mn = g_mn[tid]; int fl = g_fl[tid];
    mx = warp_max(mx); mn = warp_min(mn); fl = warp_or(fl);
    __shared__ float smx[8], smn[8]; __shared__ int sfl[8];
    if (!lane) { smx[wid] = mx; smn[wid] = mn; sfl[wid] = fl; }
    __syncthreads();
    if (tid == 0) {
        for (int w = 1; w < 8; w++) { mx = fmaxf(mx, smx[w]); mn = fminf(mn, smn[w]); fl |= sfl[w]; }
        float filled = mn - (mx - mn);
        float lo = fl ? filled : mn;
        float d1 = lo - 15.0f, d2 = mx - 15.0f;
        float Cmax = fmaxf(fmaxf(lo * lo, d1 * d1), fmaxf(mx * mx, d2 * d2));
        float invC = 1.0f / Cmax;
        Par P;
        P.filled = filled; P.invCmax = invC; P.alpha = 10.0f * invC;
        P.inv_tau = 1.0f / tau[0];
        P.c_exp2 = 2.0f * (10.0f * invC) * 1.4426950408889634f;
        g_P = P;
        g_norm = 0.0;
    }
}

// ---------------- fused prepass: top-15, sigmoids+colsums, rank-5 warm start ----------------
__global__ __launch_bounds__(512) void kPre(const float* __restrict__ scores,
                                            const float* __restrict__ w1,
                                            const float* __restrict__ w2) {
    int b = blockIdx.x, tid = threadIdx.x, lane = tid & 31, wid = tid >> 5;
    __shared__ float stv[KK];
    __shared__ float swm[16];
    __shared__ float sbc;
    __shared__ int claim;
    __shared__ float scs[16][KK];
    __shared__ float sinv[KK], lc[KK];
    __shared__ float sy[16][5];
    __shared__ float yf[5];
    __shared__ float gg[KK];

    // ---- phase A: top-15 via 15 masked argmax rounds ----
    {
        const float4* p4 = reinterpret_cast<const float4*>(scores + b * NN) + tid * 2;
        float4 a = p4[0], c4 = p4[1];
        float v[8] = {a.x, a.y, a.z, a.w, c4.x, c4.y, c4.z, c4.w};
#pragma unroll
        for (int e = 0; e < 8; e++) v[e] = fixs(v[e]);
        for (int r = 0; r < KK; r++) {
            float lm = v[0];
#pragma unroll
            for (int e = 1; e < 8; e++) lm = fmaxf(lm, v[e]);
            lm = warp_max(lm);
            if (!lane) swm[wid] = lm;
            __syncthreads();
            if (tid == 0) {
                float m = swm[0];
                for (int w = 1; w < 16; w++) m = fmaxf(m, swm[w]);
                sbc = m; claim = 0;
                stv[r] = m;
            }
            __syncthreads();
            float m = sbc;
            int idx = -1;
#pragma unroll
            for (int e = 0; e < 8; e++) if (idx < 0 && v[e] == m) idx = e;
            if (idx >= 0) {
                int old = atomicAdd(&claim, 1);
                if (old == 0) v[idx] = -3.4e38f;
            }
        }
    }
    __syncthreads();

    // ---- phase B: sigmoids + column sums ----
    {
        float itau = g_P.inv_tau;
        float cs[KK];
#pragma unroll
        for (int j = 0; j < KK; j++) cs[j] = 0.0f;
        for (int e = 0; e < 8; e++) {
            int i = tid + e * 512;
            float s = fixs(scores[b * NN + i]);
#pragma unroll
            for (int j = 0; j < KK; j++) {
                float d = fabsf(stv[j] - s) * itau;
                float ex = __expf(d);
                float sg = rcpa(1.0f + ex) + SMALLV;
                g_sig[(b * KK + j) * NN + i] = sg;
                cs[j] += sg;
            }
        }
#pragma unroll
        for (int j = 0; j < KK; j++) cs[j] = warp_sum(cs[j]);
        if (!lane) {
#pragma unroll
            for (int j = 0; j < KK; j++) scs[wid][j] = cs[j];
        }
        __syncthreads();
        if (tid < KK) {
            float a = 0.0f;
            for (int w = 0; w < 16; w++) a += scs[w][tid];
            g_colsum[b * KK + tid] = a;
            sinv[tid] = 1.0f / a;
            lc[tid] = EPSV * __logf(4096.0f * a);
        }
    }
    __syncthreads();

    // ---- phase C: rank-5 projection -> initial w (float4 loads of w2) ----
    {
        float invC = g_P.invCmax;
        float y[5] = {0, 0, 0, 0, 0};
        for (int e = 0; e < 8; e++) {
            int i = tid + e * 512;
            float s = fixs(scores[b * NN + i]);
            float bb[16];
            float rowacc = 0.0f;
#pragma unroll
            for (int c = 0; c < KK; c++) {
                float sg = g_sig[(b * KK + c) * NN + i];
                float ds = s - (float)(KK - c);
                bb[c] = ds * ds * invC + EPSV * __logf(sg) - lc[c];
                rowacc += sg * sinv[c];
            }
            float last = (1.0f - rowacc) * MUV;
            last = fminf(fmaxf(last, SMALLV), 1.0f - SMALLV);
            bb[15] = s * s * invC + EPSV * __logf(last);
#pragma unroll
            for (int r = 0; r < 5; r++) {
                const float4* wv = reinterpret_cast<const float4*>(w2 + r * 65536 + i * 16);
                float4 a0 = wv[0], a1 = wv[1], a2 = wv[2], a3 = wv[3];
                float acc = bb[0] * a0.x + bb[1] * a0.y + bb[2] * a0.z + bb[3] * a0.w;
                acc += bb[4] * a1.x + bb[5] * a1.y + bb[6] * a1.z + bb[7] * a1.w;
                acc += bb[8] * a2.x + bb[9] * a2.y + bb[10] * a2.z + bb[11] * a2.w;
                acc += bb[12] * a3.x + bb[13] * a3.y + bb[14] * a3.z + bb[15] * a3.w;
                y[r] += acc;
            }
        }
#pragma unroll
        for (int r = 0; r < 5; r++) y[r] = warp_sum(y[r]);
        if (!lane) {
#pragma unroll
            for (int r = 0; r < 5; r++) sy[wid][r] = y[r];
        }
        __syncthreads();
        if (tid < 5) {
            float a = 0.0f;
            for (int w = 0; w < 16; w++) a += sy[w][tid];
            yf[tid] = a;
        }
        __syncthreads();
        if (tid < KK) {
            float g = 0.0f;
#pragma unroll
            for (int r = 0; r < 5; r++) g += yf[r] * w1[(NN + tid) * 5 + r];
            gg[tid] = g;
        }
        __syncthreads();
        if (tid < 16) {
            int m = tid;
            float w = (m == 0) ? 1.0f
                     : __expf(10.0f * gg[KK - m] - g_P.alpha * (float)(m * m));
            g_w[b * 16 + m] = w;
        }
    }
}

// ---------------- fused main: Sinkhorn (early-exit) + output + norm ----------------
// 256 threads, 8 packed pairs/thread, full even-power table (best measured config),
// convergence check each iteration, t recomputed in epilogue (no g_t round-trip).
__global__ __launch_bounds__(256) void kMain(const float* __restrict__ scores,
                                             float* __restrict__ out) {
    int b = blockIdx.x, tid = threadIdx.x, lane = tid & 31, wid = tid >> 5;  // 8 warps
    __shared__ float sS[2][8][16];
    __shared__ float sinv[KK];
    float c2 = g_P.c_exp2;
    const float2* sc2 = reinterpret_cast<const float2*>(scores + b * NN);

    // p values as 8 packed pairs; even powers x^2..x^14 (iteration-invariant)
    ull X[8];
    ull P[8][7];
#pragma unroll
    for (int p = 0; p < 8; p++) {
        float2 s = sc2[tid + p * 256];
        float xlo = exp2f(c2 * fixs(s.x));
        float xhi = exp2f(c2 * fixs(s.y));
        ull x = pk2(xlo, xhi);
        X[p] = x;
        ull x2 = mul2(x, x);
        P[p][0] = x2;
#pragma unroll
        for (int j = 1; j < 7; j++) P[p][j] = mul2(P[p][j - 1], x2);
    }
    ull W[16];
#pragma unroll
    for (int m = 0; m < 16; m++) { float v = g_w[b * 16 + m]; W[m] = pk2(v, v); }
    float wold = g_w[b * 16 + (lane & 15)];

    for (int it = 0; it < NITER; it++) {
        ull S[16];
#pragma unroll
        for (int m = 0; m < 16; m++) S[m] = 0ull;
#pragma unroll
        for (int p = 0; p < 8; p++) {
            ull x2 = P[p][0];
            // H = A(x^2) + x*B(x^2)
            ull A = W[14], B = W[15];
#pragma unroll
            for (int j = 6; j >= 1; j--) {
                A = fma2(A, x2, W[2 * j]);
                B = fma2(B, x2, W[2 * j + 1]);
            }
            A = fma2(A, x2, W[0]);
            B = fma2(B, x2, W[1]);
            ull H = fma2(X[p], B, A);
            float hlo, hhi; upk2(hlo, hhi, H);
            float tlo = MUV * rcpa(hlo);
            float thi = MUV * rcpa(hhi);
            ull t = pk2(tlo, thi);
            ull tx = mul2(t, X[p]);
            S[0] = add2(S[0], t);
            S[1] = add2(S[1], tx);
#pragma unroll
            for (int j = 1; j < 8; j++) {
                S[2 * j]     = fma2(t,  P[p][j - 1], S[2 * j]);
                S[2 * j + 1] = fma2(tx, P[p][j - 1], S[2 * j + 1]);
            }
        }
        // pairwise halves
        float v[16];
#pragma unroll
        for (int m = 0; m < 16; m++) { float lo, hi; upk2(lo, hi, S[m]); v[m] = lo + hi; }
        // index-matched butterfly: value m's bit j follows lane bit j
        float u8[8];
#pragma unroll
        for (int q = 0; q < 8; q++) {
            float keep = (lane & 1) ? v[2 * q + 1] : v[2 * q];
            float send = (lane & 1) ? v[2 * q] : v[2 * q + 1];
            u8[q] = keep + __shfl_xor_sync(0xffffffffu, send, 1);
        }
        float u4[4];
#pragma unroll
        for (int q = 0; q < 4; q++) {
            float keep = (lane & 2) ? u8[2 * q + 1] : u8[2 * q];
            float send = (lane & 2) ? u8[2 * q] : u8[2 * q + 1];
            u4[q] = keep + __shfl_xor_sync(0xffffffffu, send, 2);
        }
        float u2v[2];
#pragma unroll
        for (int q = 0; q < 2; q++) {
            float keep = (lane & 4) ? u4[2 * q + 1] : u4[2 * q];
            float send = (lane & 4) ? u4[2 * q] : u4[2 * q + 1];
            u2v[q] = keep + __shfl_xor_sync(0xffffffffu, send, 4);
        }
        float k1 = (lane & 8) ? u2v[1] : u2v[0];
        float s1 = (lane & 8) ? u2v[0] : u2v[1];
        float u1f = k1 + __shfl_xor_sync(0xffffffffu, s1, 8);
        float tot = u1f + __shfl_xor_sync(0xffffffffu, u1f, 16);
        // tot = warp total for index m = lane & 15
        int par = it & 1;
        if (lane < 16) sS[par][wid][lane] = tot;
        __syncthreads();
        int m = lane & 15;
        float a = 0.0f;
#pragma unroll
        for (int q = 0; q < 8; q++) a += sS[par][q][m];
        float nu = (m == 0) ? NU0 : MUV;
        float wv = nu * rcpa(a);
        // convergence measure (identical across all lanes/warps -> uniform branch)
        float delta = fabsf(wv - wold) * rcpa(fmaxf(fabsf(wold), 1e-30f));
        wold = wv;
        float md = warp_max(delta);
#pragma unroll
        for (int m2 = 0; m2 < 16; m2++) {
            float x = __shfl_sync(0xffffffffu, wv, m2);
            W[m2] = pk2(x, x);
        }
        if (md < CONVTOL) break;
    }

    // ---- epilogue: recompute t from final W, Gamma, output A, norm ----
    if (tid < KK) sinv[tid] = 1.0f / g_colsum[b * KK + tid];
    __syncthreads();
    float nacc = 0.0f;
#pragma unroll
    for (int p = 0; p < 8; p++) {
        ull x2 = P[p][0];
        ull A = W[14], B = W[15];
#pragma unroll
        for (int j = 6; j >= 1; j--) {
            A = fma2(A, x2, W[2 * j]);
            B = fma2(B, x2, W[2 * j + 1]);
        }
        A = fma2(A, x2, W[0]);
        B = fma2(B, x2, W[1]);
        ull H = fma2(X[p], B, A);
        float hlo, hhi; upk2(hlo, hhi, H);
        ull t = pk2(MUV * rcpa(hlo), MUV * rcpa(hhi));
        ull tx = mul2(t, X[p]);

        int e0 = 2 * (tid + p * 256);
        float* Ao0 = out + ((size_t)(b * NN + e0)) * 15;
        float* Ao1 = Ao0 + 15;
        float racc0 = 0.0f, racc1 = 0.0f;
        float g0lo = 0.0f, g0hi = 0.0f;
#pragma unroll
        for (int m = 0; m < 16; m++) {
            ull base;
            if (m == 0) base = t;
            else if (m == 1) base = tx;
            else if ((m & 1) == 0) base = mul2(t, P[p][m / 2 - 1]);
            else base = mul2(tx, P[p][(m - 1) / 2 - 1]);
            ull g = mul2(base, W[m]);
            float glo, ghi; upk2(glo, ghi, g);
            if (m == 0) { g0lo = glo; g0hi = ghi; }
            else {
                int c = 15 - m;
                Ao0[c] = 4096.0f * glo;
                Ao1[c] = 4096.0f * ghi;
                const float2 sg2 = *reinterpret_cast<const float2*>(
                    &g_sig[(b * KK + c) * NN + e0]);
                float sn0 = sg2.x * sinv[c];
                float sn1 = sg2.y * sinv[c];
                racc0 += sn0; racc1 += sn1;
                float d0 = glo - sn0 * MUV;
                float d1 = ghi - sn1 * MUV;
                nacc += d0 * d0 + d1 * d1;
            }
        }
        float l0 = fminf(fmaxf((1.0f - racc0) * MUV, SMALLV), 1.0f - SMALLV);
        float l1 = fminf(fmaxf((1.0f - racc1) * MUV, SMALLV), 1.0f - SMALLV);
        float d0 = g0lo - l0, d1 = g0hi - l1;
        nacc += d0 * d0 + d1 * d1;
    }
    nacc = warp_sum(nacc);
    __shared__ float snrm[8];
    if (!lane) snrm[wid] = nacc;
    __syncthreads();
    if (tid == 0) {
        float a = 0.0f;
        for (int q = 0; q < 8; q++) a += snrm[q];
        atomicAdd(&g_norm, (double)a);
    }
}

__global__ void kFin(float* __restrict__ out, int out_size) {
    if (threadIdx.x == 0) out[out_size - 1] = sqrtf((float)g_norm);
}

extern "C" void kernel_launch(void* const* d_in, const int* in_sizes, int n_in,
                              void* d_out, int out_size) {
    const float* scores = (const float*)d_in[0];
    const float* tau    = (const float*)d_in[1];
    const float* w1     = (const float*)d_in[2];
    const float* w2     = (const float*)d_in[3];
    float* out = (float*)d_out;
    kA1<<<256, 256>>>(scores);
    kA2<<<1, 256>>>(tau);
    kPre<<<NB, 512>>>(scores, w1, w2);
    kMain<<<NB, 256>>>(scores, out);
    kFin<<<1, 1>>>(out, out_size);
}

// round 10
// speedup vs baseline: 3.8643x; 1.0711x over previous
#include <cuda_runtime.h>
#include <math.h>

#define NB 128
#define NN 4096
#define KK 15
#define EPSV 0.1f
#define SMALLV 1e-20f
#define MUV 2.44140625e-4f   /* 1/4096 */
#define NU0 (4081.0f/4096.0f)
#define NITER 200
#define CONVTOL 1e-6f

typedef unsigned long long ull;

// ---------------- device scratch (static, no allocation) ----------------
__device__ float g_sig[NB * KK * NN];   // sigmoid+SMALL, layout [b][j][i]
__device__ float g_colsum[NB * KK];     // per-(b,j) column sums of sig
__device__ float g_w[NB * 16];          // Sinkhorn state w_m (init, then final)
__device__ float g_mx[256], g_mn[256];
__device__ int   g_fl[256];
__device__ double g_norm;

struct Par { float filled, invCmax, alpha, inv_tau, c_exp2; };
__device__ Par g_P;

// ---------------- helpers ----------------
__device__ __forceinline__ float warp_sum(float v) {
#pragma unroll
    for (int o = 16; o > 0; o >>= 1) v += __shfl_xor_sync(0xffffffffu, v, o);
    return v;
}
__device__ __forceinline__ float warp_max(float v) {
#pragma unroll
    for (int o = 16; o > 0; o >>= 1) v = fmaxf(v, __shfl_xor_sync(0xffffffffu, v, o));
    return v;
}
__device__ __forceinline__ float warp_min(float v) {
#pragma unroll
    for (int o = 16; o > 0; o >>= 1) v = fminf(v, __shfl_xor_sync(0xffffffffu, v, o));
    return v;
}
__device__ __forceinline__ int warp_or(int v) {
#pragma unroll
    for (int o = 16; o > 0; o >>= 1) v |= __shfl_xor_sync(0xffffffffu, v, o);
    return v;
}
__device__ __forceinline__ float rcpa(float x) {
    float y; asm("rcp.approx.f32 %0, %1;" : "=f"(y) : "f"(x)); return y;
}
__device__ __forceinline__ float fixs(float s) {
    return (isinf(s) && s < 0.0f) ? g_P.filled : s;
}

// ---------------- packed f32x2 (sm_103a) ----------------
__device__ __forceinline__ ull pk2(float lo, float hi) {
    ull r; asm("mov.b64 %0, {%1,%2};" : "=l"(r) : "f"(lo), "f"(hi)); return r;
}
__device__ __forceinline__ void upk2(float& lo, float& hi, ull v) {
    asm("mov.b64 {%0,%1}, %2;" : "=f"(lo), "=f"(hi) : "l"(v));
}
__device__ __forceinline__ ull fma2(ull a, ull b, ull c) {
    ull d; asm("fma.rn.f32x2 %0, %1, %2, %3;" : "=l"(d) : "l"(a), "l"(b), "l"(c)); return d;
}
__device__ __forceinline__ ull mul2(ull a, ull b) {
    ull d; asm("mul.rn.f32x2 %0, %1, %2;" : "=l"(d) : "l"(a), "l"(b)); return d;
}
__device__ __forceinline__ ull add2(ull a, ull b) {
    ull d; asm("add.rn.f32x2 %0, %1, %2;" : "=l"(d) : "l"(a), "l"(b)); return d;
}

// ---------------- A1: global min/max partials ----------------
__global__ void kA1(const float* __restrict__ scores) {
    int tid = threadIdx.x;
    int base = blockIdx.x * 2048 + tid * 8;
    const float4* p4 = reinterpret_cast<const float4*>(scores + base);
    float4 a = p4[0], b = p4[1];
    float vs[8] = {a.x, a.y, a.z, a.w, b.x, b.y, b.z, b.w};
    float mx = -3.4e38f, mn = 3.4e38f; int fl = 0;
#pragma unroll
    for (int t = 0; t < 8; t++) {
        float x = vs[t];
        if (isinf(x) && x < 0.0f) fl = 1;
        else mn = fminf(mn, x);
        mx = fmaxf(mx, x);
    }
    mx = warp_max(mx); mn = warp_min(mn); fl = warp_or(fl);
    __shared__ float smx[8], smn[8]; __shared__ int sfl[8];
    int lane = tid & 31, wid = tid >> 5;
    if (!lane) { smx[wid] = mx; smn[wid] = mn; sfl[wid] = fl; }
    __syncthreads();
    if (tid == 0) {
        for (int w = 1; w < 8; w++) { mx = fmaxf(mx, smx[w]); mn = fminf(mn, smn[w]); fl |= sfl[w]; }
        g_mx[blockIdx.x] = mx; g_mn[blockIdx.x] = mn; g_fl[blockIdx.x] = fl;
    }
}

// ---------------- A2: finalize scalar params ----------------
__global__ void kA2(const float* __restrict__ tau) {
    int tid = threadIdx.x, lane = tid & 31, wid = tid >> 5;
    float mx = g_mx[tid], mn = g_mn[tid]; int fl = g_fl[tid];
    mx = warp_max(mx); mn = warp_min(mn); fl = warp_or(fl);
    __shared__ float smx[8], smn[8]; __shared__ int sfl[8];
    if (!lane) { smx[wid] = mx; smn[wid] = mn; sfl[wid] = fl; }
    __syncthreads();
    if (tid == 0) {
        for (int w = 1; w < 8; w++) { mx = fmaxf(mx, smx[w]); mn = fminf(mn, smn[w]); fl |= sfl[w]; }
        float filled = mn - (mx - mn);
        float lo = fl ? filled : mn;
        float d1 = lo - 15.0f, d2 = mx - 15.0f;
        float Cmax = fmaxf(fmaxf(lo * lo, d1 * d1), fmaxf(mx * mx, d2 * d2));
        float invC = 1.0f / Cmax;
        Par P;
        P.filled = filled; P.invCmax = invC; P.alpha = 10.0f * invC;
        P.inv_tau = 1.0f / tau[0];
        P.c_exp2 = 2.0f * (10.0f * invC) * 1.4426950408889634f;
        g_P = P;
        g_norm = 0.0;
    }
}

// ---------------- fused prepass: top-15, sigmoids+colsums, rank-5 warm start ----------------
// Phase C uses the rank structure of w2: w2[r, i*16+c] = (vf[i,r]+vg[c,r])/s_r,
// with w1 = V/s containing vf/s (rows < N) and vg/s (rows >= N). Hence
//   y_r = sum_i w1[i,r]*rowsum_i + sum_{c<15} w1[N+c,r]*colsumB_c
// and w2 is never read.
__global__ __launch_bounds__(512) void kPre(const float* __restrict__ scores,
                                            const float* __restrict__ w1) {
    int b = blockIdx.x, tid = threadIdx.x, lane = tid & 31, wid = tid >> 5;
    __shared__ float stv[KK];
    __shared__ float swm[16];
    __shared__ float sbc;
    __shared__ int claim;
    __shared__ float scs[16][16];
    __shared__ float sinv[KK], lc[KK];
    __shared__ float sy[16][5];
    __shared__ float yf[5];
    __shared__ float ccol[KK];
    __shared__ float gg[KK];

    // ---- phase A: top-15 via 15 masked argmax rounds ----
    {
        const float4* p4 = reinterpret_cast<const float4*>(scores + b * NN) + tid * 2;
        float4 a = p4[0], c4 = p4[1];
        float v[8] = {a.x, a.y, a.z, a.w, c4.x, c4.y, c4.z, c4.w};
#pragma unroll
        for (int e = 0; e < 8; e++) v[e] = fixs(v[e]);
        for (int r = 0; r < KK; r++) {
            float lm = v[0];
#pragma unroll
            for (int e = 1; e < 8; e++) lm = fmaxf(lm, v[e]);
            lm = warp_max(lm);
            if (!lane) swm[wid] = lm;
            __syncthreads();
            if (tid == 0) {
                float m = swm[0];
                for (int w = 1; w < 16; w++) m = fmaxf(m, swm[w]);
                sbc = m; claim = 0;
                stv[r] = m;
            }
            __syncthreads();
            float m = sbc;
            int idx = -1;
#pragma unroll
            for (int e = 0; e < 8; e++) if (idx < 0 && v[e] == m) idx = e;
            if (idx >= 0) {
                int old = atomicAdd(&claim, 1);
                if (old == 0) v[idx] = -3.4e38f;
            }
        }
    }
    __syncthreads();

    // ---- phase B: sigmoids + column sums of sig ----
    {
        float itau = g_P.inv_tau;
        float cs[KK];
#pragma unroll
        for (int j = 0; j < KK; j++) cs[j] = 0.0f;
        for (int e = 0; e < 8; e++) {
            int i = tid + e * 512;
            float s = fixs(scores[b * NN + i]);
#pragma unroll
            for (int j = 0; j < KK; j++) {
                float d = fabsf(stv[j] - s) * itau;
                float ex = __expf(d);
                float sg = rcpa(1.0f + ex) + SMALLV;
                g_sig[(b * KK + j) * NN + i] = sg;
                cs[j] += sg;
            }
        }
#pragma unroll
        for (int j = 0; j < KK; j++) cs[j] = warp_sum(cs[j]);
        if (!lane) {
#pragma unroll
            for (int j = 0; j < KK; j++) scs[wid][j] = cs[j];
        }
        __syncthreads();
        if (tid < KK) {
            float a = 0.0f;
            for (int w = 0; w < 16; w++) a += scs[w][tid];
            g_colsum[b * KK + tid] = a;
            sinv[tid] = 1.0f / a;
            lc[tid] = EPSV * __logf(4096.0f * a);
        }
    }
    __syncthreads();

    // ---- phase C: rank-5 projection via rowsums/colsums of b ----
    {
        float invC = g_P.invCmax;
        float y[5] = {0, 0, 0, 0, 0};
        float cb[KK];                 // per-thread partial column sums of b
#pragma unroll
        for (int c = 0; c < KK; c++) cb[c] = 0.0f;
        for (int e = 0; e < 8; e++) {
            int i = tid + e * 512;
            float s = fixs(scores[b * NN + i]);
            float rowacc = 0.0f;
            float R = 0.0f;           // rowsum of b over all 16 columns
#pragma unroll
            for (int c = 0; c < KK; c++) {
                float sg = g_sig[(b * KK + c) * NN + i];
                float ds = s - (float)(KK - c);
                float bic = ds * ds * invC + EPSV * __logf(sg) - lc[c];
                rowacc += sg * sinv[c];
                R += bic;
                cb[c] += bic;
            }
            float last = (1.0f - rowacc) * MUV;
            last = fminf(fmaxf(last, SMALLV), 1.0f - SMALLV);
            float b15 = s * s * invC + EPSV * __logf(last);
            R += b15;
            const float* wr = w1 + (size_t)i * 5;
#pragma unroll
            for (int r = 0; r < 5; r++) y[r] += R * wr[r];
        }
#pragma unroll
        for (int r = 0; r < 5; r++) y[r] = warp_sum(y[r]);
#pragma unroll
        for (int c = 0; c < KK; c++) cb[c] = warp_sum(cb[c]);
        if (!lane) {
#pragma unroll
            for (int r = 0; r < 5; r++) sy[wid][r] = y[r];
#pragma unroll
            for (int c = 0; c < KK; c++) scs[wid][c] = cb[c];
        }
        __syncthreads();
        if (tid < KK) {
            float a = 0.0f;
            for (int w = 0; w < 16; w++) a += scs[w][tid];
            ccol[tid] = a;
        }
        __syncthreads();
        if (tid < 5) {
            float a = 0.0f;
            for (int w = 0; w < 16; w++) a += sy[w][tid];
            // add the vg-side term: sum_{c<15} w1[(N+c),r] * colsumB_c
            for (int c = 0; c < KK; c++) a += ccol[c] * w1[(size_t)(NN + c) * 5 + tid];
            yf[tid] = a;
        }
        __syncthreads();
        if (tid < KK) {
            float g = 0.0f;
#pragma unroll
            for (int r = 0; r < 5; r++) g += yf[r] * w1[(size_t)(NN + tid) * 5 + r];
            gg[tid] = g;
        }
        __syncthreads();
        if (tid < 16) {
            int m = tid;
            float w = (m == 0) ? 1.0f
                     : __expf(10.0f * gg[KK - m] - g_P.alpha * (float)(m * m));
            g_w[b * 16 + m] = w;
        }
    }
}

// ---------------- main: Sinkhorn loop only (early exit), stores final W ----------------
__global__ __launch_bounds__(256) void kMain(const float* __restrict__ scores) {
    int b = blockIdx.x, tid = threadIdx.x, lane = tid & 31, wid = tid >> 5;  // 8 warps
    __shared__ float sS[2][8][16];
    float c2 = g_P.c_exp2;
    const float2* sc2 = reinterpret_cast<const float2*>(scores + b * NN);

    ull X[8];
    ull P[8][7];
#pragma unroll
    for (int p = 0; p < 8; p++) {
        float2 s = sc2[tid + p * 256];
        float xlo = exp2f(c2 * fixs(s.x));
        float xhi = exp2f(c2 * fixs(s.y));
        ull x = pk2(xlo, xhi);
        X[p] = x;
        ull x2 = mul2(x, x);
        P[p][0] = x2;
#pragma unroll
        for (int j = 1; j < 7; j++) P[p][j] = mul2(P[p][j - 1], x2);
    }
    ull W[16];
#pragma unroll
    for (int m = 0; m < 16; m++) { float v = g_w[b * 16 + m]; W[m] = pk2(v, v); }
    float wold = g_w[b * 16 + (lane & 15)];

    for (int it = 0; it < NITER; it++) {
        ull S[16];
#pragma unroll
        for (int m = 0; m < 16; m++) S[m] = 0ull;
#pragma unroll
        for (int p = 0; p < 8; p++) {
            ull x2 = P[p][0];
            ull A = W[14], B = W[15];
#pragma unroll
            for (int j = 6; j >= 1; j--) {
                A = fma2(A, x2, W[2 * j]);
                B = fma2(B, x2, W[2 * j + 1]);
            }
            A = fma2(A, x2, W[0]);
            B = fma2(B, x2, W[1]);
            ull H = fma2(X[p], B, A);
            float hlo, hhi; upk2(hlo, hhi, H);
            ull t = pk2(MUV * rcpa(hlo), MUV * rcpa(hhi));
            ull tx = mul2(t, X[p]);
            S[0] = add2(S[0], t);
            S[1] = add2(S[1], tx);
#pragma unroll
            for (int j = 1; j < 8; j++) {
                S[2 * j]     = fma2(t,  P[p][j - 1], S[2 * j]);
                S[2 * j + 1] = fma2(tx, P[p][j - 1], S[2 * j + 1]);
            }
        }
        float v[16];
#pragma unroll
        for (int m = 0; m < 16; m++) { float lo, hi; upk2(lo, hi, S[m]); v[m] = lo + hi; }
        float u8[8];
#pragma unroll
        for (int q = 0; q < 8; q++) {
            float keep = (lane & 1) ? v[2 * q + 1] : v[2 * q];
            float send = (lane & 1) ? v[2 * q] : v[2 * q + 1];
            u8[q] = keep + __shfl_xor_sync(0xffffffffu, send, 1);
        }
        float u4[4];
#pragma unroll
        for (int q = 0; q < 4; q++) {
            float keep = (lane & 2) ? u8[2 * q + 1] : u8[2 * q];
            float send = (lane & 2) ? u8[2 * q] : u8[2 * q + 1];
            u4[q] = keep + __shfl_xor_sync(0xffffffffu, send, 2);
        }
        float u2v[2];
#pragma unroll
        for (int q = 0; q < 2; q++) {
            float keep = (lane & 4) ? u4[2 * q + 1] : u4[2 * q];
            float send = (lane & 4) ? u4[2 * q] : u4[2 * q + 1];
            u2v[q] = keep + __shfl_xor_sync(0xffffffffu, send, 4);
        }
        float k1 = (lane & 8) ? u2v[1] : u2v[0];
        float s1 = (lane & 8) ? u2v[0] : u2v[1];
        float u1f = k1 + __shfl_xor_sync(0xffffffffu, s1, 8);
        float tot = u1f + __shfl_xor_sync(0xffffffffu, u1f, 16);
        int par = it & 1;
        if (lane < 16) sS[par][wid][lane] = tot;
        __syncthreads();
        int m = lane & 15;
        float a = 0.0f;
#pragma unroll
        for (int q = 0; q < 8; q++) a += sS[par][q][m];
        float nu = (m == 0) ? NU0 : MUV;
        float wv = nu * rcpa(a);
        float delta = fabsf(wv - wold) * rcpa(fmaxf(fabsf(wold), 1e-30f));
        wold = wv;
        float md = warp_max(delta);
#pragma unroll
        for (int m2 = 0; m2 < 16; m2++) {
            float x = __shfl_sync(0xffffffffu, wv, m2);
            W[m2] = pk2(x, x);
        }
        if (md < CONVTOL) break;
    }
    if (tid < 16) g_w[b * 16 + tid] = wold;
}

// ---------------- output: Gamma, A, norm — full-chip grid (NB*4 CTAs) ----------------
__global__ __launch_bounds__(256) void kOut(const float* __restrict__ scores,
                                            float* __restrict__ out) {
    int blk = blockIdx.x;
    int b = blk >> 2, q = blk & 3;
    int tid = threadIdx.x, lane = tid & 31, wid = tid >> 5;
    __shared__ float sWs[16], sinv[KK];
    if (tid < 16) sWs[tid] = g_w[b * 16 + tid];
    if (tid < KK) sinv[tid] = 1.0f / g_colsum[b * KK + tid];
    __syncthreads();
    ull W[16];
#pragma unroll
    for (int m = 0; m < 16; m++) W[m] = pk2(sWs[m], sWs[m]);
    float c2 = g_P.c_exp2;
    const float2* sc2 = reinterpret_cast<const float2*>(scores + b * NN);
    float nacc = 0.0f;
#pragma unroll
    for (int p = 0; p < 2; p++) {
        int pairIdx = q * 512 + p * 256 + tid;   // 0..2047
        float2 s = sc2[pairIdx];
        float xlo = exp2f(c2 * fixs(s.x));
        float xhi = exp2f(c2 * fixs(s.y));
        ull x = pk2(xlo, xhi);
        ull x2 = mul2(x, x);
        ull P[7];
        P[0] = x2;
#pragma unroll
        for (int j = 1; j < 7; j++) P[j] = mul2(P[j - 1], x2);
        // t = MU / H(x)
        ull A = W[14], B = W[15];
#pragma unroll
        for (int j = 6; j >= 1; j--) {
            A = fma2(A, x2, W[2 * j]);
            B = fma2(B, x2, W[2 * j + 1]);
        }
        A = fma2(A, x2, W[0]);
        B = fma2(B, x2, W[1]);
        ull H = fma2(x, B, A);
        float hlo, hhi; upk2(hlo, hhi, H);
        ull t = pk2(MUV * rcpa(hlo), MUV * rcpa(hhi));
        ull tx = mul2(t, x);

        int e0 = 2 * pairIdx;
        float* Ao0 = out + ((size_t)(b * NN + e0)) * 15;
        float* Ao1 = Ao0 + 15;
        float racc0 = 0.0f, racc1 = 0.0f;
        float g0lo = 0.0f, g0hi = 0.0f;
#pragma unroll
        for (int m = 0; m < 16; m++) {
            ull base;
            if (m == 0) base = t;
            else if (m == 1) base = tx;
            else if ((m & 1) == 0) base = mul2(t, P[m / 2 - 1]);
            else base = mul2(tx, P[(m - 1) / 2 - 1]);
            ull g = mul2(base, W[m]);
            float glo, ghi; upk2(glo, ghi, g);
            if (m == 0) { g0lo = glo; g0hi = ghi; }
            else {
                int c = 15 - m;
                Ao0[c] = 4096.0f * glo;
                Ao1[c] = 4096.0f * ghi;
                const float2 sg2 = *reinterpret_cast<const float2*>(
                    &g_sig[(b * KK + c) * NN + e0]);
                float sn0 = sg2.x * sinv[c];
                float sn1 = sg2.y * sinv[c];
                racc0 += sn0; racc1 += sn1;
                float d0 = glo - sn0 * MUV;
                float d1 = ghi - sn1 * MUV;
                nacc += d0 * d0 + d1 * d1;
            }
        }
        float l0 = fminf(fmaxf((1.0f - racc0) * MUV, SMALLV), 1.0f - SMALLV);
        float l1 = fminf(fmaxf((1.0f - racc1) * MUV, SMALLV), 1.0f - SMALLV);
        float d0 = g0lo - l0, d1 = g0hi - l1;
        nacc += d0 * d0 + d1 * d1;
    }
    nacc = warp_sum(nacc);
    __shared__ float snrm[8];
    if (!lane) snrm[wid] = nacc;
    __syncthreads();
    if (tid == 0) {
        float a = 0.0f;
        for (int w = 0; w < 8; w++) a += snrm[w];
        atomicAdd(&g_norm, (double)a);
    }
}

__global__ void kFin(float* __restrict__ out, int out_size) {
    if (threadIdx.x == 0) out[out_size - 1] = sqrtf((float)g_norm);
}

extern "C" void kernel_launch(void* const* d_in, const int* in_sizes, int n_in,
                              void* d_out, int out_size) {
    const float* scores = (const float*)d_in[0];
    const float* tau    = (const float*)d_in[1];
    const float* w1     = (const float*)d_in[2];
    float* out = (float*)d_out;
    kA1<<<256, 256>>>(scores);
    kA2<<<1, 256>>>(tau);
    kPre<<<NB, 512>>>(scores, w1);
    kMain<<<NB, 256>>>(scores);
    kOut<<<NB * 4, 256>>>(scores, out);
    kFin<<<1, 1>>>(out, out_size);
}

// round 13
// speedup vs baseline: 4.2967x; 1.1119x over previous
#include <cuda_runtime.h>
#include <math.h>

#define NB 128
#define NN 4096
#define KK 15
#define EPSV 0.1f
#define SMALLV 1e-20f
#define MUV 2.44140625e-4f   /* 1/4096 */
#define NU0 (4081.0f/4096.0f)
#define NITER 200
#define CONVTOL 1e-6f
#define LOG2E 1.4426950408889634f

typedef unsigned long long ull;

// ---------------- device scratch (static, no allocation) ----------------
__device__ float g_sig[NB * KK * NN];   // sigmoid+SMALL, layout [b][j][i]
__device__ float g_colsum[NB * KK];     // per-(b,j) column sums of sig (atomic)
__device__ float g_tv[NB * KK];         // top-15 values per row (descending)
__device__ float g_y[NB * 5];           // partial y_r (atomic)
__device__ float g_cb[NB * KK];         // partial colsum of b (atomic)
__device__ float g_w[NB * 16];          // final Sinkhorn state (kMain -> kOut)
__device__ float g_mx[256], g_mn[256];
__device__ int   g_fl[256];
__device__ double g_norm;
__device__ unsigned g_cnt;

struct Par { float filled, invCmax, alpha, inv_tau, c_exp2, itau2; };
__device__ Par g_P;

// ---------------- helpers ----------------
__device__ __forceinline__ float warp_sum(float v) {
#pragma unroll
    for (int o = 16; o > 0; o >>= 1) v += __shfl_xor_sync(0xffffffffu, v, o);
    return v;
}
__device__ __forceinline__ float warp_max(float v) {
#pragma unroll
    for (int o = 16; o > 0; o >>= 1) v = fmaxf(v, __shfl_xor_sync(0xffffffffu, v, o));
    return v;
}
__device__ __forceinline__ float warp_min(float v) {
#pragma unroll
    for (int o = 16; o > 0; o >>= 1) v = fminf(v, __shfl_xor_sync(0xffffffffu, v, o));
    return v;
}
__device__ __forceinline__ int warp_or(int v) {
#pragma unroll
    for (int o = 16; o > 0; o >>= 1) v |= __shfl_xor_sync(0xffffffffu, v, o);
    return v;
}
__device__ __forceinline__ float rcpa(float x) {
    float y; asm("rcp.approx.f32 %0, %1;" : "=f"(y) : "f"(x)); return y;
}
__device__ __forceinline__ float fixs(float s) {
    return (isinf(s) && s < 0.0f) ? g_P.filled : s;
}

// ---------------- packed f32x2 (sm_103a) ----------------
__device__ __forceinline__ ull pk2(float lo, float hi) {
    ull r; asm("mov.b64 %0, {%1,%2};" : "=l"(r) : "f"(lo), "f"(hi)); return r;
}
__device__ __forceinline__ void upk2(float& lo, float& hi, ull v) {
    asm("mov.b64 {%0,%1}, %2;" : "=f"(lo), "=f"(hi) : "l"(v));
}
__device__ __forceinline__ ull fma2(ull a, ull b, ull c) {
    ull d; asm("fma.rn.f32x2 %0, %1, %2, %3;" : "=l"(d) : "l"(a), "l"(b), "l"(c)); return d;
}
__device__ __forceinline__ ull mul2(ull a, ull b) {
    ull d; asm("mul.rn.f32x2 %0, %1, %2;" : "=l"(d) : "l"(a), "l"(b)); return d;
}
__device__ __forceinline__ ull add2(ull a, ull b) {
    ull d; asm("add.rn.f32x2 %0, %1, %2;" : "=l"(d) : "l"(a), "l"(b)); return d;
}

// ---------------- A1: global min/max partials ----------------
__global__ void kA1(const float* __restrict__ scores) {
    int tid = threadIdx.x;
    int base = blockIdx.x * 2048 + tid * 8;
    const float4* p4 = reinterpret_cast<const float4*>(scores + base);
    float4 a = p4[0], b = p4[1];
    float vs[8] = {a.x, a.y, a.z, a.w, b.x, b.y, b.z, b.w};
    float mx = -3.4e38f, mn = 3.4e38f; int fl = 0;
#pragma unroll
    for (int t = 0; t < 8; t++) {
        float x = vs[t];
        if (isinf(x) && x < 0.0f) fl = 1;
        else mn = fminf(mn, x);
        mx = fmaxf(mx, x);
    }
    mx = warp_max(mx); mn = warp_min(mn); fl = warp_or(fl);
    __shared__ float smx[8], smn[8]; __shared__ int sfl[8];
    int lane = tid & 31, wid = tid >> 5;
    if (!lane) { smx[wid] = mx; smn[wid] = mn; sfl[wid] = fl; }
    __syncthreads();
    if (tid == 0) {
        for (int w = 1; w < 8; w++) { mx = fmaxf(mx, smx[w]); mn = fminf(mn, smn[w]); fl |= sfl[w]; }
        g_mx[blockIdx.x] = mx; g_mn[blockIdx.x] = mn; g_fl[blockIdx.x] = fl;
    }
}

// ---------------- A2: finalize scalar params + zero accumulators ----------------
__global__ void kA2(const float* __restrict__ tau) {
    int tid = threadIdx.x, lane = tid & 31, wid = tid >> 5;
    // zero the atomic accumulators (128*15 + 128*5 + 128*15 floats)
    for (int i = tid; i < NB * KK; i += 256) { g_colsum[i] = 0.0f; g_cb[i] = 0.0f; }
    for (int i = tid; i < NB * 5; i += 256) g_y[i] = 0.0f;
    float mx = g_mx[tid], mn = g_mn[tid]; int fl = g_fl[tid];
    mx = warp_max(mx); mn = warp_min(mn); fl = warp_or(fl);
    __shared__ float smx[8], smn[8]; __shared__ int sfl[8];
    if (!lane) { smx[wid] = mx; smn[wid] = mn; sfl[wid] = fl; }
    __syncthreads();
    if (tid == 0) {
        for (int w = 1; w < 8; w++) { mx = fmaxf(mx, smx[w]); mn = fminf(mn, smn[w]); fl |= sfl[w]; }
        float filled = mn - (mx - mn);
        float lo = fl ? filled : mn;
        float d1 = lo - 15.0f, d2 = mx - 15.0f;
        float Cmax = fmaxf(fmaxf(lo * lo, d1 * d1), fmaxf(mx * mx, d2 * d2));
        float invC = 1.0f / Cmax;
        Par P;
        P.filled = filled; P.invCmax = invC; P.alpha = 10.0f * invC;
        P.inv_tau = 1.0f / tau[0];
        P.c_exp2 = 2.0f * (10.0f * invC) * LOG2E;
        P.itau2 = P.inv_tau * LOG2E;
        g_P = P;
        g_norm = 0.0;
        g_cnt = 0u;
    }
}

// ---------------- top-15 per row (15 masked-argmax rounds) ----------------
__global__ __launch_bounds__(512) void kTop(const float* __restrict__ scores) {
    int b = blockIdx.x, tid = threadIdx.x, lane = tid & 31, wid = tid >> 5;
    const float4* p4 = reinterpret_cast<const float4*>(scores + b * NN) + tid * 2;
    float4 a = p4[0], c4 = p4[1];
    float v[8] = {a.x, a.y, a.z, a.w, c4.x, c4.y, c4.z, c4.w};
#pragma unroll
    for (int e = 0; e < 8; e++) v[e] = fixs(v[e]);
    __shared__ float swm[16];
    __shared__ float sbc;
    __shared__ int claim;
    for (int r = 0; r < KK; r++) {
        float lm = v[0];
#pragma unroll
        for (int e = 1; e < 8; e++) lm = fmaxf(lm, v[e]);
        lm = warp_max(lm);
        if (!lane) swm[wid] = lm;
        __syncthreads();
        if (tid == 0) {
            float m = swm[0];
            for (int w = 1; w < 16; w++) m = fmaxf(m, swm[w]);
            sbc = m; claim = 0;
            g_tv[b * KK + r] = m;
        }
        __syncthreads();
        float m = sbc;
        int idx = -1;
#pragma unroll
        for (int e = 0; e < 8; e++) if (idx < 0 && v[e] == m) idx = e;
        if (idx >= 0) {
            int old = atomicAdd(&claim, 1);
            if (old == 0) v[idx] = -3.4e38f;
        }
    }
}

// ---------------- B: sigmoids + colsums, 4 CTAs per row ----------------
// e^{|tv_j - s|/tau} = max(Ej/E, E/Ej) with Ej per-row constants:
// 1 exp + 16 rcp per element instead of 15 exp + 15 rcp.
__global__ __launch_bounds__(256) void kB(const float* __restrict__ scores) {
    int blk = blockIdx.x;
    int b = blk >> 2, q = blk & 3;
    int tid = threadIdx.x, lane = tid & 31, wid = tid >> 5;
    __shared__ float sEj[KK], srEj[KK];
    float it2 = g_P.itau2;
    if (tid < KK) {
        float E = exp2f(g_tv[b * KK + tid] * it2);
        sEj[tid] = E;
        srEj[tid] = 1.0f / E;
    }
    __syncthreads();
    float cs[KK];
#pragma unroll
    for (int j = 0; j < KK; j++) cs[j] = 0.0f;
    for (int e = 0; e < 4; e++) {
        int i = q * 1024 + e * 256 + tid;
        float s = fixs(scores[b * NN + i]);
        float E = exp2f(s * it2);
        float rE = rcpa(E);
#pragma unroll
        for (int j = 0; j < KK; j++) {
            float ed = fmaxf(sEj[j] * rE, E * srEj[j]);
            float sg = rcpa(1.0f + ed) + SMALLV;
            g_sig[(b * KK + j) * NN + i] = sg;
            cs[j] += sg;
        }
    }
#pragma unroll
    for (int j = 0; j < KK; j++) cs[j] = warp_sum(cs[j]);
    __shared__ float scs[8][KK];
    if (!lane) {
#pragma unroll
        for (int j = 0; j < KK; j++) scs[wid][j] = cs[j];
    }
    __syncthreads();
    if (tid < KK) {
        float a = 0.0f;
        for (int w = 0; w < 8; w++) a += scs[w][tid];
        atomicAdd(&g_colsum[b * KK + tid], a);
    }
}

// ---------------- C: warm-start partial sums, 4 CTAs per row ----------------
// y_r = sum_i w1[i,r]*R_i + sum_c w1[N+c,r]*cb_c (assembled in kMain prologue).
// R_i uses closed-form sum of squares: sum_c (s-a_c)^2 = 16s^2-240s+1240.
// cb_c quadratic part from (sum s, sum s^2) closed form.
__global__ __launch_bounds__(256) void kC(const float* __restrict__ scores,
                                          const float* __restrict__ w1) {
    int blk = blockIdx.x;
    int b = blk >> 2, q = blk & 3;
    int tid = threadIdx.x, lane = tid & 31, wid = tid >> 5;
    __shared__ float sinv[KK], lc[KK];
    __shared__ float sSL;
    if (tid < KK) {
        float a = g_colsum[b * KK + tid];
        sinv[tid] = 1.0f / a;
        lc[tid] = EPSV * __logf(4096.0f * a);
    }
    __syncthreads();
    if (tid == 0) {
        float a = 0.0f;
        for (int c = 0; c < KK; c++) a += lc[c];
        sSL = a;
    }
    __syncthreads();
    float invC = g_P.invCmax;
    float SL = sSL;
    float y[5] = {0, 0, 0, 0, 0};
    float colLog[KK];
#pragma unroll
    for (int c = 0; c < KK; c++) colLog[c] = 0.0f;
    float ssum = 0.0f, ssum2 = 0.0f;
    for (int e = 0; e < 4; e++) {
        int i = q * 1024 + e * 256 + tid;
        float s = fixs(scores[b * NN + i]);
        float rowacc = 0.0f, rowLog = 0.0f;
#pragma unroll
        for (int c = 0; c < KK; c++) {
            float sg = g_sig[(b * KK + c) * NN + i];
            float l = __logf(sg);
            rowacc += sg * sinv[c];
            rowLog += l;
            colLog[c] += l;
        }
        ssum += s; ssum2 += s * s;
        float last = fminf(fmaxf((1.0f - rowacc) * MUV, SMALLV), 1.0f - SMALLV);
        float lnlast = __logf(last);
        float R = (16.0f * s * s - 240.0f * s + 1240.0f) * invC
                + EPSV * (rowLog + lnlast) - SL;
        const float* wr = w1 + (size_t)i * 5;
#pragma unroll
        for (int r = 0; r < 5; r++) y[r] += R * wr[r];
    }
#pragma unroll
    for (int r = 0; r < 5; r++) y[r] = warp_sum(y[r]);
#pragma unroll
    for (int c = 0; c < KK; c++) colLog[c] = warp_sum(colLog[c]);
    ssum = warp_sum(ssum);
    ssum2 = warp_sum(ssum2);
    __shared__ float sy[8][5], scl[8][KK], sss[8], sss2[8];
    if (!lane) {
#pragma unroll
        for (int r = 0; r < 5; r++) sy[wid][r] = y[r];
#pragma unroll
        for (int c = 0; c < KK; c++) scl[wid][c] = colLog[c];
        sss[wid] = ssum; sss2[wid] = ssum2;
    }
    __syncthreads();
    if (tid < 5) {
        float a = 0.0f;
        for (int w = 0; w < 8; w++) a += sy[w][tid];
        atomicAdd(&g_y[b * 5 + tid], a);
    }
    if (tid >= 32 && tid < 32 + KK) {
        int c = tid - 32;
        float cl = 0.0f, S1 = 0.0f, S2 = 0.0f;
        for (int w = 0; w < 8; w++) { cl += scl[w][c]; S1 += sss[w]; S2 += sss2[w]; }
        float a = (float)(KK - c);   // anchor for column c
        float cb = (S2 - 2.0f * a * S1 + 1024.0f * a * a) * invC
                 + EPSV * cl - 1024.0f * lc[c];
        atomicAdd(&g_cb[b * KK + c], cb);
    }
}

// ---------------- main: warm-start assembly + Sinkhorn loop (early exit) ----------------
__global__ __launch_bounds__(256) void kMain(const float* __restrict__ scores,
                                             const float* __restrict__ w1) {
    int b = blockIdx.x, tid = threadIdx.x, lane = tid & 31, wid = tid >> 5;  // 8 warps
    __shared__ float sS[2][8][16];
    __shared__ float yf[5], ggs[KK], sWinit[16];
    float c2 = g_P.c_exp2;
    const float2* sc2 = reinterpret_cast<const float2*>(scores + b * NN);

    // assemble initial w from partial sums
    if (tid < 5) {
        float a = g_y[b * 5 + tid];
        for (int c = 0; c < KK; c++)
            a += g_cb[b * KK + c] * w1[(size_t)(NN + c) * 5 + tid];
        yf[tid] = a;
    }
    __syncthreads();
    if (tid < KK) {
        float g = 0.0f;
#pragma unroll
        for (int r = 0; r < 5; r++) g += yf[r] * w1[(size_t)(NN + tid) * 5 + r];
        ggs[tid] = g;
    }
    __syncthreads();
    if (tid < 16) {
        sWinit[tid] = (tid == 0) ? 1.0f
            : __expf(10.0f * ggs[KK - tid] - g_P.alpha * (float)(tid * tid));
    }

    ull X[8];
    ull P[8][7];
#pragma unroll
    for (int p = 0; p < 8; p++) {
        float2 s = sc2[tid + p * 256];
        float xlo = exp2f(c2 * fixs(s.x));
        float xhi = exp2f(c2 * fixs(s.y));
        ull x = pk2(xlo, xhi);
        X[p] = x;
        ull x2 = mul2(x, x);
        P[p][0] = x2;
#pragma unroll
        for (int j = 1; j < 7; j++) P[p][j] = mul2(P[p][j - 1], x2);
    }
    __syncthreads();
    ull W[16];
#pragma unroll
    for (int m = 0; m < 16; m++) { float v = sWinit[m]; W[m] = pk2(v, v); }
    float wold = sWinit[lane & 15];

    for (int it = 0; it < NITER; it++) {
        ull S[16];
#pragma unroll
        for (int m = 0; m < 16; m++) S[m] = 0ull;
#pragma unroll
        for (int p = 0; p < 8; p++) {
            ull x2 = P[p][0];
            ull A = W[14], B = W[15];
#pragma unroll
            for (int j = 6; j >= 1; j--) {
                A = fma2(A, x2, W[2 * j]);
                B = fma2(B, x2, W[2 * j + 1]);
            }
            A = fma2(A, x2, W[0]);
            B = fma2(B, x2, W[1]);
            ull H = fma2(X[p], B, A);
            float hlo, hhi; upk2(hlo, hhi, H);
            ull t = pk2(MUV * rcpa(hlo), MUV * rcpa(hhi));
            ull tx = mul2(t, X[p]);
            S[0] = add2(S[0], t);
            S[1] = add2(S[1], tx);
#pragma unroll
            for (int j = 1; j < 8; j++) {
                S[2 * j]     = fma2(t,  P[p][j - 1], S[2 * j]);
                S[2 * j + 1] = fma2(tx, P[p][j - 1], S[2 * j + 1]);
            }
        }
        float v[16];
#pragma unroll
        for (int m = 0; m < 16; m++) { float lo, hi; upk2(lo, hi, S[m]); v[m] = lo + hi; }
        float u8[8];
#pragma unroll
        for (int q = 0; q < 8; q++) {
            float keep = (lane & 1) ? v[2 * q + 1] : v[2 * q];
            float send = (lane & 1) ? v[2 * q] : v[2 * q + 1];
            u8[q] = keep + __shfl_xor_sync(0xffffffffu, send, 1);
        }
        float u4[4];
#pragma unroll
        for (int q = 0; q < 4; q++) {
            float keep = (lane & 2) ? u8[2 * q + 1] : u8[2 * q];
            float send = (lane & 2) ? u8[2 * q] : u8[2 * q + 1];
            u4[q] = keep + __shfl_xor_sync(0xffffffffu, send, 2);
        }
        float u2v[2];
#pragma unroll
        for (int q = 0; q < 2; q++) {
            float keep = (lane & 4) ? u4[2 * q + 1] : u4[2 * q];
            float send = (lane & 4) ? u4[2 * q] : u4[2 * q + 1];
            u2v[q] = keep + __shfl_xor_sync(0xffffffffu, send, 4);
        }
        float k1 = (lane & 8) ? u2v[1] : u2v[0];
        float s1 = (lane & 8) ? u2v[0] : u2v[1];
        float u1f = k1 + __shfl_xor_sync(0xffffffffu, s1, 8);
        float tot = u1f + __shfl_xor_sync(0xffffffffu, u1f, 16);
        int par = it & 1;
        if (lane < 16) sS[par][wid][lane] = tot;
        __syncthreads();
        int m = lane & 15;
        float a = 0.0f;
#pragma unroll
        for (int q = 0; q < 8; q++) a += sS[par][q][m];
        float nu = (m == 0) ? NU0 : MUV;
        float wv = nu * rcpa(a);
        float delta = fabsf(wv - wold) * rcpa(fmaxf(fabsf(wold), 1e-30f));
        wold = wv;
        float md = warp_max(delta);
#pragma unroll
        for (int m2 = 0; m2 < 16; m2++) {
            float x = __shfl_sync(0xffffffffu, wv, m2);
            W[m2] = pk2(x, x);
        }
        if (md < CONVTOL) break;
    }
    if (tid < 16) g_w[b * 16 + tid] = wold;
}

// ---------------- output: Gamma, A, norm — grid NB*8; last block writes sqrt ----------------
__global__ __launch_bounds__(256) void kOut(const float* __restrict__ scores,
                                            float* __restrict__ out, int out_size) {
    int blk = blockIdx.x;
    int b = blk >> 3, q = blk & 7;
    int tid = threadIdx.x, lane = tid & 31, wid = tid >> 5;
    __shared__ float sWs[16], sinv[KK];
    if (tid < 16) sWs[tid] = g_w[b * 16 + tid];
    if (tid < KK) sinv[tid] = 1.0f / g_colsum[b * KK + tid];
    __syncthreads();
    ull W[16];
#pragma unroll
    for (int m = 0; m < 16; m++) W[m] = pk2(sWs[m], sWs[m]);
    float c2 = g_P.c_exp2;
    const float2* sc2 = reinterpret_cast<const float2*>(scores + b * NN);
    float nacc = 0.0f;
    {
        int pairIdx = q * 256 + tid;   // 0..2047
        float2 s = sc2[pairIdx];
        float xlo = exp2f(c2 * fixs(s.x));
        float xhi = exp2f(c2 * fixs(s.y));
        ull x = pk2(xlo, xhi);
        ull x2 = mul2(x, x);
        ull P[7];
        P[0] = x2;
#pragma unroll
        for (int j = 1; j < 7; j++) P[j] = mul2(P[j - 1], x2);
        ull A = W[14], B = W[15];
#pragma unroll
        for (int j = 6; j >= 1; j--) {
            A = fma2(A, x2, W[2 * j]);
            B = fma2(B, x2, W[2 * j + 1]);
        }
        A = fma2(A, x2, W[0]);
        B = fma2(B, x2, W[1]);
        ull H = fma2(x, B, A);
        float hlo, hhi; upk2(hlo, hhi, H);
        ull t = pk2(MUV * rcpa(hlo), MUV * rcpa(hhi));
        ull tx = mul2(t, x);

        int e0 = 2 * pairIdx;
        float* Ao0 = out + ((size_t)(b * NN + e0)) * 15;
        float* Ao1 = Ao0 + 15;
        float racc0 = 0.0f, racc1 = 0.0f;
        float g0lo = 0.0f, g0hi = 0.0f;
#pragma unroll
        for (int m = 0; m < 16; m++) {
            ull base;
            if (m == 0) base = t;
            else if (m == 1) base = tx;
            else if ((m & 1) == 0) base = mul2(t, P[m / 2 - 1]);
            else base = mul2(tx, P[(m - 1) / 2 - 1]);
            ull g = mul2(base, W[m]);
            float glo, ghi; upk2(glo, ghi, g);
            if (m == 0) { g0lo = glo; g0hi = ghi; }
            else {
                int c = 15 - m;
                Ao0[c] = 4096.0f * glo;
                Ao1[c] = 4096.0f * ghi;
                const float2 sg2 = *reinterpret_cast<const float2*>(
                    &g_sig[(b * KK + c) * NN + e0]);
                float sn0 = sg2.x * sinv[c];
                float sn1 = sg2.y * sinv[c];
                racc0 += sn0; racc1 += sn1;
                float d0 = glo - sn0 * MUV;
                float d1 = ghi - sn1 * MUV;
                nacc += d0 * d0 + d1 * d1;
            }
        }
        float l0 = fminf(fmaxf((1.0f - racc0) * MUV, SMALLV), 1.0f - SMALLV);
        float l1 = fminf(fmaxf((1.0f - racc1) * MUV, SMALLV), 1.0f - SMALLV);
        float d0 = g0lo - l0, d1 = g0hi - l1;
        nacc += d0 * d0 + d1 * d1;
    }
    nacc = warp_sum(nacc);
    __shared__ float snrm[8];
    if (!lane) snrm[wid] = nacc;
    __syncthreads();
    if (tid == 0) {
        float a = 0.0f;
        for (int w = 0; w < 8; w++) a += snrm[w];
        atomicAdd(&g_norm, (double)a);
        __threadfence();
        unsigned tkt = atomicAdd(&g_cnt, 1u);
        if (tkt == gridDim.x - 1) {
            double nv = atomicAdd(&g_norm, 0.0);
            out[out_size - 1] = sqrtf((float)nv);
        }
    }
}

extern "C" void kernel_launch(void* const* d_in, const int* in_sizes, int n_in,
                              void* d_out, int out_size) {
    const float* scores = (const float*)d_in[0];
    const float* tau    = (const float*)d_in[1];
    const float* w1     = (const float*)d_in[2];
    float* out = (float*)d_out;
    kA1<<<256, 256>>>(scores);
    kA2<<<1, 256>>>(tau);
    kTop<<<NB, 512>>>(scores);
    kB<<<NB * 4, 256>>>(scores);
    kC<<<NB * 4, 256>>>(scores, w1);
    kMain<<<NB, 256>>>(scores, w1);
    kOut<<<NB * 8, 256>>>(scores, out, out_size);
}